// round 1
// baseline (speedup 1.0000x reference)
#include <cuda_runtime.h>

#define NU   100000
#define NI   50000
#define NN   (NU + NI)          // 150000
#define EMB  64
#define NE   3000000            // edges per direction (total dir. edges = 2*NE)
#define FDIM 1024
#define NB   16384

// ---------------- static device scratch (no allocations allowed) ----------------
__device__ float g_x0[(size_t)NN * EMB];
__device__ float g_x1[(size_t)NN * EMB];
__device__ float g_acc[(size_t)NN * EMB];
__device__ int   g_deg[NN];
__device__ int   g_off[NN];
__device__ int   g_cur[NN];
__device__ float g_dinv[NN];
__device__ unsigned long long g_csr[(size_t)2 * NE];   // packed {norm(fp32)<<32 | src}
__device__ float g_proj[(size_t)NB * EMB];

// ---------------- graph build ----------------
__global__ void k_zero_deg() {
    int n = blockIdx.x * blockDim.x + threadIdx.x;
    if (n < NN) g_deg[n] = 0;
}

__global__ void k_init(const float* __restrict__ Gu, const float* __restrict__ Gi) {
    int i = blockIdx.x * blockDim.x + threadIdx.x;
    if (i < NN * EMB) {
        float v = (i < NU * EMB) ? Gu[i] : Gi[i - NU * EMB];
        g_x0[i]  = v;
        g_acc[i] = v;
    }
}

__global__ void k_deg(const int* __restrict__ ue, const int* __restrict__ ie) {
    int e = blockIdx.x * blockDim.x + threadIdx.x;
    if (e < NE) {
        atomicAdd(&g_deg[ue[e]], 1);
        atomicAdd(&g_deg[ie[e] + NU], 1);
    }
}

__global__ void k_dinv() {
    int n = blockIdx.x * blockDim.x + threadIdx.x;
    if (n < NN) {
        int d = g_deg[n];
        g_dinv[n] = (d > 0) ? rsqrtf((float)d) : 0.0f;
    }
}

// single-block exclusive scan of g_deg -> g_off, also initializes g_cur
__global__ void __launch_bounds__(1024) k_scan() {
    __shared__ int s[1024];
    const int CH = (NN + 1023) / 1024;   // 147
    int t   = threadIdx.x;
    int beg = t * CH;
    int end = min(beg + CH, NN);
    int sum = 0;
    for (int i = beg; i < end; i++) sum += g_deg[i];
    s[t] = sum;
    __syncthreads();
    for (int o = 1; o < 1024; o <<= 1) {
        int v = (t >= o) ? s[t - o] : 0;
        __syncthreads();
        s[t] += v;
        __syncthreads();
    }
    int run = (t > 0) ? s[t - 1] : 0;
    for (int i = beg; i < end; i++) {
        g_off[i] = run;
        g_cur[i] = run;
        run += g_deg[i];
    }
}

__global__ void k_scatter(const int* __restrict__ ue, const int* __restrict__ ie) {
    int e = blockIdx.x * blockDim.x + threadIdx.x;
    if (e < NE) {
        int u  = ue[e];
        int it = ie[e] + NU;
        float nm = g_dinv[u] * g_dinv[it];
        unsigned long long nb = ((unsigned long long)__float_as_uint(nm)) << 32;
        int p1 = atomicAdd(&g_cur[it], 1);
        g_csr[p1] = nb | (unsigned int)u;
        int p2 = atomicAdd(&g_cur[u], 1);
        g_csr[p2] = nb | (unsigned int)it;
    }
}

// ---------------- propagation: one warp per destination node ----------------
__global__ void __launch_bounds__(256) k_prop(int dir) {
    const float* __restrict__ xin = dir ? g_x1 : g_x0;
    float* __restrict__ xout      = dir ? g_x0 : g_x1;

    int w    = (blockIdx.x * blockDim.x + threadIdx.x) >> 5;
    int lane = threadIdx.x & 31;
    if (w >= NN) return;

    int cnt = g_deg[w];
    const unsigned long long* __restrict__ csr = g_csr + g_off[w];

    float s0 = 0.0f, s1 = 0.0f;
    int i = 0;
    for (; i + 4 <= cnt; i += 4) {
        unsigned long long e0 = csr[i],     e1 = csr[i + 1];
        unsigned long long e2 = csr[i + 2], e3 = csr[i + 3];
        int r0 = (int)(unsigned int)e0, r1 = (int)(unsigned int)e1;
        int r2 = (int)(unsigned int)e2, r3 = (int)(unsigned int)e3;
        float n0 = __uint_as_float((unsigned int)(e0 >> 32));
        float n1 = __uint_as_float((unsigned int)(e1 >> 32));
        float n2 = __uint_as_float((unsigned int)(e2 >> 32));
        float n3 = __uint_as_float((unsigned int)(e3 >> 32));
        float a0 = xin[(size_t)r0 * EMB + lane],      b0 = xin[(size_t)r0 * EMB + lane + 32];
        float a1 = xin[(size_t)r1 * EMB + lane],      b1 = xin[(size_t)r1 * EMB + lane + 32];
        float a2 = xin[(size_t)r2 * EMB + lane],      b2 = xin[(size_t)r2 * EMB + lane + 32];
        float a3 = xin[(size_t)r3 * EMB + lane],      b3 = xin[(size_t)r3 * EMB + lane + 32];
        s0 = fmaf(a0, n0, s0); s1 = fmaf(b0, n0, s1);
        s0 = fmaf(a1, n1, s0); s1 = fmaf(b1, n1, s1);
        s0 = fmaf(a2, n2, s0); s1 = fmaf(b2, n2, s1);
        s0 = fmaf(a3, n3, s0); s1 = fmaf(b3, n3, s1);
    }
    for (; i < cnt; i++) {
        unsigned long long e0 = csr[i];
        int r0   = (int)(unsigned int)e0;
        float n0 = __uint_as_float((unsigned int)(e0 >> 32));
        s0 = fmaf(xin[(size_t)r0 * EMB + lane],      n0, s0);
        s1 = fmaf(xin[(size_t)r0 * EMB + lane + 32], n0, s1);
    }

    size_t o = (size_t)w * EMB + lane;
    xout[o]      = s0;
    xout[o + 32] = s1;
    g_acc[o]      += s0;
    g_acc[o + 32] += s1;
}

// ---------------- projection GEMM: proj = F[items] @ W^T + b ----------------
// block = 256 threads handles 64 items x 64 outputs, tiled over FDIM in chunks of 32
__global__ void __launch_bounds__(256) k_gemm(const float* __restrict__ F,
                                              const float* __restrict__ W,
                                              const float* __restrict__ bias,
                                              const int* __restrict__ items) {
    __shared__ float Fs[64][33];
    __shared__ float Ws[32][65];
    __shared__ int   si[64];

    int t    = threadIdx.x;
    int base = blockIdx.x * 64;
    if (t < 64) si[t] = items[base + t];
    __syncthreads();

    int tx = t & 15;    // output-k group
    int ty = t >> 4;    // item group
    float acc[4][4] = {};

    for (int f0 = 0; f0 < FDIM; f0 += 32) {
        #pragma unroll
        for (int j = 0; j < 8; j++) {
            int idx = j * 256 + t;
            int row = idx >> 5, col = idx & 31;
            Fs[row][col] = F[(size_t)si[row] * FDIM + f0 + col];
        }
        #pragma unroll
        for (int j = 0; j < 8; j++) {
            int idx = j * 256 + t;
            int k = idx >> 5, c = idx & 31;
            Ws[c][k] = W[(size_t)k * FDIM + f0 + c];
        }
        __syncthreads();
        #pragma unroll
        for (int c = 0; c < 32; c++) {
            float fv[4], wv[4];
            #pragma unroll
            for (int ii = 0; ii < 4; ii++) fv[ii] = Fs[ty + 16 * ii][c];
            #pragma unroll
            for (int jj = 0; jj < 4; jj++) wv[jj] = Ws[c][tx + 16 * jj];
            #pragma unroll
            for (int ii = 0; ii < 4; ii++)
                #pragma unroll
                for (int jj = 0; jj < 4; jj++)
                    acc[ii][jj] = fmaf(fv[ii], wv[jj], acc[ii][jj]);
        }
        __syncthreads();
    }

    #pragma unroll
    for (int ii = 0; ii < 4; ii++) {
        int r = ty + 16 * ii;
        #pragma unroll
        for (int jj = 0; jj < 4; jj++) {
            int k = tx + 16 * jj;
            g_proj[(size_t)(base + r) * EMB + k] = acc[ii][jj] + bias[k];
        }
    }
}

// ---------------- final scoring: one warp per batch element ----------------
__global__ void __launch_bounds__(256) k_score(const float* __restrict__ Tu,
                                               const int* __restrict__ users,
                                               const int* __restrict__ items,
                                               float* __restrict__ out) {
    int w    = (blockIdx.x * blockDim.x + threadIdx.x) >> 5;
    int lane = threadIdx.x & 31;
    if (w >= NB) return;

    int u  = users[w];
    int it = items[w];
    const float* au = g_acc + (size_t)u * EMB;
    const float* ai = g_acc + (size_t)(NU + it) * EMB;
    const float* tu = Tu + (size_t)u * EMB;
    const float* pr = g_proj + (size_t)w * EMB;

    float a0 = au[lane], a1 = au[lane + 32];
    float b0 = ai[lane], b1 = ai[lane + 32];
    float p0 = pr[lane], p1 = pr[lane + 32];
    float t0 = tu[lane], t1 = tu[lane + 32];

    float d1 = a0 * b0 + a1 * b1;            // gamma dot (times 16)
    float ss = p0 * p0 + p1 * p1;            // |proj|^2
    float d2 = t0 * p0 + t1 * p1;            // theta . proj

    #pragma unroll
    for (int o = 16; o > 0; o >>= 1) {
        d1 += __shfl_xor_sync(0xffffffffu, d1, o);
        ss += __shfl_xor_sync(0xffffffffu, ss, o);
        d2 += __shfl_xor_sync(0xffffffffu, d2, o);
    }
    if (lane == 0) {
        float inv = 1.0f / fmaxf(sqrtf(ss), 1e-12f);
        out[w] = d1 * (1.0f / 16.0f) + d2 * inv;   // (acc/4).(acc/4) = dot/16
    }
}

// ---------------- launch ----------------
extern "C" void kernel_launch(void* const* d_in, const int* in_sizes, int n_in,
                              void* d_out, int out_size) {
    const float* Gu    = (const float*)d_in[0];
    const float* Gi    = (const float*)d_in[1];
    const float* Tu    = (const float*)d_in[2];
    const float* F     = (const float*)d_in[3];
    const float* W     = (const float*)d_in[4];
    const float* bias  = (const float*)d_in[5];
    const int*   ue    = (const int*)d_in[6];
    const int*   ie    = (const int*)d_in[7];
    const int*   users = (const int*)d_in[8];
    const int*   items = (const int*)d_in[9];
    float*       out   = (float*)d_out;

    (void)in_sizes; (void)n_in; (void)out_size;

    k_zero_deg<<<(NN + 255) / 256, 256>>>();
    k_deg<<<(NE + 255) / 256, 256>>>(ue, ie);
    k_dinv<<<(NN + 255) / 256, 256>>>();
    k_scan<<<1, 1024>>>();
    k_scatter<<<(NE + 255) / 256, 256>>>(ue, ie);
    k_init<<<(NN * EMB + 255) / 256, 256>>>(Gu, Gi);

    k_prop<<<(NN * 32 + 255) / 256, 256>>>(0);   // x0 -> x1
    k_prop<<<(NN * 32 + 255) / 256, 256>>>(1);   // x1 -> x0
    k_prop<<<(NN * 32 + 255) / 256, 256>>>(0);   // x0 -> x1

    k_gemm<<<NB / 64, 256>>>(F, W, bias, items);
    k_score<<<(NB * 32 + 255) / 256, 256>>>(Tu, users, items, out);
}

// round 2
// speedup vs baseline: 1.3977x; 1.3977x over previous
#include <cuda_runtime.h>

#define NU   100000
#define NI   50000
#define NN   (NU + NI)          // 150000
#define EMB  64
#define NE   3000000            // edges per direction (total dir. edges = 2*NE)
#define FDIM 1024
#define NB   16384
#define NPART ((NN + 255) / 256)   // 586

// ---------------- static device scratch (no allocations allowed) ----------------
__device__ float g_x0[(size_t)NN * EMB];
__device__ float g_x1[(size_t)NN * EMB];
__device__ float g_acc[(size_t)NN * EMB];
__device__ int   g_deg[NN];
__device__ int   g_off[NN];
__device__ int   g_cur[NN];
__device__ float g_dinv[NN];
__device__ int   g_part[1024];
__device__ unsigned long long g_csr[(size_t)2 * NE];   // packed {norm(fp32)<<32 | src}
__device__ float g_proj[(size_t)NB * EMB];

// ---------------- graph build ----------------
__global__ void k_zero_deg() {
    int n = blockIdx.x * blockDim.x + threadIdx.x;
    if (n < NN) g_deg[n] = 0;
}

__global__ void k_init(const float* __restrict__ Gu, const float* __restrict__ Gi) {
    int i = blockIdx.x * blockDim.x + threadIdx.x;
    if (i < NN * EMB / 4) {
        const float4* src = (i < NU * EMB / 4) ? (const float4*)Gu
                                               : (const float4*)Gi - (size_t)NU * EMB / 4;
        float4 v = src[i];
        ((float4*)g_x0)[i]  = v;
        ((float4*)g_acc)[i] = v;
    }
}

__global__ void k_deg(const int* __restrict__ ue, const int* __restrict__ ie) {
    int e = blockIdx.x * blockDim.x + threadIdx.x;
    if (e < NE) {
        atomicAdd(&g_deg[ue[e]], 1);
        atomicAdd(&g_deg[ie[e] + NU], 1);
    }
}

// phase A: per-block sum of degrees (also computes dinv)
__global__ void __launch_bounds__(256) k_part() {
    __shared__ int s[256];
    int t = threadIdx.x;
    int n = blockIdx.x * 256 + t;
    int d = (n < NN) ? g_deg[n] : 0;
    if (n < NN) g_dinv[n] = (d > 0) ? rsqrtf((float)d) : 0.0f;
    s[t] = d;
    __syncthreads();
    #pragma unroll
    for (int o = 128; o > 0; o >>= 1) {
        if (t < o) s[t] += s[t + o];
        __syncthreads();
    }
    if (t == 0) g_part[blockIdx.x] = s[0];
}

// phase B: single-block exclusive scan of the 586 partials
__global__ void __launch_bounds__(1024) k_scanpart() {
    __shared__ int s[1024];
    int t = threadIdx.x;
    int v = (t < NPART) ? g_part[t] : 0;
    s[t] = v;
    __syncthreads();
    #pragma unroll
    for (int o = 1; o < 1024; o <<= 1) {
        int u = (t >= o) ? s[t - o] : 0;
        __syncthreads();
        s[t] += u;
        __syncthreads();
    }
    if (t < NPART) g_part[t] = s[t] - v;   // exclusive
}

// phase C: per-block local scan + partial base -> offsets
__global__ void __launch_bounds__(256) k_off() {
    __shared__ int s[256];
    int t = threadIdx.x;
    int n = blockIdx.x * 256 + t;
    int d = (n < NN) ? g_deg[n] : 0;
    s[t] = d;
    __syncthreads();
    #pragma unroll
    for (int o = 1; o < 256; o <<= 1) {
        int u = (t >= o) ? s[t - o] : 0;
        __syncthreads();
        s[t] += u;
        __syncthreads();
    }
    if (n < NN) {
        int off = g_part[blockIdx.x] + s[t] - d;
        g_off[n] = off;
        g_cur[n] = off;
    }
}

__global__ void k_scatter(const int* __restrict__ ue, const int* __restrict__ ie) {
    int e = blockIdx.x * blockDim.x + threadIdx.x;
    if (e < NE) {
        int u  = ue[e];
        int it = ie[e] + NU;
        float nm = g_dinv[u] * g_dinv[it];
        unsigned long long nb = ((unsigned long long)__float_as_uint(nm)) << 32;
        int p1 = atomicAdd(&g_cur[it], 1);
        g_csr[p1] = nb | (unsigned int)u;
        int p2 = atomicAdd(&g_cur[u], 1);
        g_csr[p2] = nb | (unsigned int)it;
    }
}

// ---------------- propagation: one warp per destination node, float2 gathers ----------------
__global__ void __launch_bounds__(256) k_prop(int dir) {
    const float2* __restrict__ xin = dir ? (const float2*)g_x1 : (const float2*)g_x0;
    float2* __restrict__ xout      = dir ? (float2*)g_x0 : (float2*)g_x1;

    int w    = (blockIdx.x * blockDim.x + threadIdx.x) >> 5;
    int lane = threadIdx.x & 31;
    if (w >= NN) return;

    int cnt = g_deg[w];
    const unsigned long long* __restrict__ csr = g_csr + g_off[w];

    float s0 = 0.0f, s1 = 0.0f;
    int i = 0;
    for (; i + 4 <= cnt; i += 4) {
        unsigned long long e0 = csr[i],     e1 = csr[i + 1];
        unsigned long long e2 = csr[i + 2], e3 = csr[i + 3];
        int r0 = (int)(unsigned int)e0, r1 = (int)(unsigned int)e1;
        int r2 = (int)(unsigned int)e2, r3 = (int)(unsigned int)e3;
        float n0 = __uint_as_float((unsigned int)(e0 >> 32));
        float n1 = __uint_as_float((unsigned int)(e1 >> 32));
        float n2 = __uint_as_float((unsigned int)(e2 >> 32));
        float n3 = __uint_as_float((unsigned int)(e3 >> 32));
        float2 v0 = xin[(size_t)r0 * 32 + lane];
        float2 v1 = xin[(size_t)r1 * 32 + lane];
        float2 v2 = xin[(size_t)r2 * 32 + lane];
        float2 v3 = xin[(size_t)r3 * 32 + lane];
        s0 = fmaf(v0.x, n0, s0); s1 = fmaf(v0.y, n0, s1);
        s0 = fmaf(v1.x, n1, s0); s1 = fmaf(v1.y, n1, s1);
        s0 = fmaf(v2.x, n2, s0); s1 = fmaf(v2.y, n2, s1);
        s0 = fmaf(v3.x, n3, s0); s1 = fmaf(v3.y, n3, s1);
    }
    for (; i < cnt; i++) {
        unsigned long long e0 = csr[i];
        int r0   = (int)(unsigned int)e0;
        float n0 = __uint_as_float((unsigned int)(e0 >> 32));
        float2 v0 = xin[(size_t)r0 * 32 + lane];
        s0 = fmaf(v0.x, n0, s0);
        s1 = fmaf(v0.y, n0, s1);
    }

    size_t o = (size_t)w * 32 + lane;
    float2 r; r.x = s0; r.y = s1;
    xout[o] = r;
    float2* ac = (float2*)g_acc;
    float2 a = ac[o];
    a.x += s0; a.y += s1;
    ac[o] = a;
}

// ---------------- projection GEMM: proj = F[items] @ W^T + b ----------------
__global__ void __launch_bounds__(256) k_gemm(const float* __restrict__ F,
                                              const float* __restrict__ W,
                                              const float* __restrict__ bias,
                                              const int* __restrict__ items) {
    __shared__ float Fs[64][33];
    __shared__ float Ws[32][65];
    __shared__ int   si[64];

    int t    = threadIdx.x;
    int base = blockIdx.x * 64;
    if (t < 64) si[t] = items[base + t];
    __syncthreads();

    int tx = t & 15;    // output-k group
    int ty = t >> 4;    // item group
    float acc[4][4] = {};

    for (int f0 = 0; f0 < FDIM; f0 += 32) {
        #pragma unroll
        for (int j = 0; j < 8; j++) {
            int idx = j * 256 + t;
            int row = idx >> 5, col = idx & 31;
            Fs[row][col] = F[(size_t)si[row] * FDIM + f0 + col];
        }
        #pragma unroll
        for (int j = 0; j < 8; j++) {
            int idx = j * 256 + t;
            int k = idx >> 5, c = idx & 31;
            Ws[c][k] = W[(size_t)k * FDIM + f0 + c];
        }
        __syncthreads();
        #pragma unroll
        for (int c = 0; c < 32; c++) {
            float fv[4], wv[4];
            #pragma unroll
            for (int ii = 0; ii < 4; ii++) fv[ii] = Fs[ty + 16 * ii][c];
            #pragma unroll
            for (int jj = 0; jj < 4; jj++) wv[jj] = Ws[c][tx + 16 * jj];
            #pragma unroll
            for (int ii = 0; ii < 4; ii++)
                #pragma unroll
                for (int jj = 0; jj < 4; jj++)
                    acc[ii][jj] = fmaf(fv[ii], wv[jj], acc[ii][jj]);
        }
        __syncthreads();
    }

    #pragma unroll
    for (int ii = 0; ii < 4; ii++) {
        int r = ty + 16 * ii;
        #pragma unroll
        for (int jj = 0; jj < 4; jj++) {
            int k = tx + 16 * jj;
            g_proj[(size_t)(base + r) * EMB + k] = acc[ii][jj] + bias[k];
        }
    }
}

// ---------------- final scoring: one warp per batch element ----------------
__global__ void __launch_bounds__(256) k_score(const float* __restrict__ Tu,
                                               const int* __restrict__ users,
                                               const int* __restrict__ items,
                                               float* __restrict__ out) {
    int w    = (blockIdx.x * blockDim.x + threadIdx.x) >> 5;
    int lane = threadIdx.x & 31;
    if (w >= NB) return;

    int u  = users[w];
    int it = items[w];
    const float* au = g_acc + (size_t)u * EMB;
    const float* ai = g_acc + (size_t)(NU + it) * EMB;
    const float* tu = Tu + (size_t)u * EMB;
    const float* pr = g_proj + (size_t)w * EMB;

    float a0 = au[lane], a1 = au[lane + 32];
    float b0 = ai[lane], b1 = ai[lane + 32];
    float p0 = pr[lane], p1 = pr[lane + 32];
    float t0 = tu[lane], t1 = tu[lane + 32];

    float d1 = a0 * b0 + a1 * b1;            // gamma dot (times 16)
    float ss = p0 * p0 + p1 * p1;            // |proj|^2
    float d2 = t0 * p0 + t1 * p1;            // theta . proj

    #pragma unroll
    for (int o = 16; o > 0; o >>= 1) {
        d1 += __shfl_xor_sync(0xffffffffu, d1, o);
        ss += __shfl_xor_sync(0xffffffffu, ss, o);
        d2 += __shfl_xor_sync(0xffffffffu, d2, o);
    }
    if (lane == 0) {
        float inv = 1.0f / fmaxf(sqrtf(ss), 1e-12f);
        out[w] = d1 * (1.0f / 16.0f) + d2 * inv;   // (acc/4).(acc/4) = dot/16
    }
}

// ---------------- launch ----------------
extern "C" void kernel_launch(void* const* d_in, const int* in_sizes, int n_in,
                              void* d_out, int out_size) {
    const float* Gu    = (const float*)d_in[0];
    const float* Gi    = (const float*)d_in[1];
    const float* Tu    = (const float*)d_in[2];
    const float* F     = (const float*)d_in[3];
    const float* W     = (const float*)d_in[4];
    const float* bias  = (const float*)d_in[5];
    const int*   ue    = (const int*)d_in[6];
    const int*   ie    = (const int*)d_in[7];
    const int*   users = (const int*)d_in[8];
    const int*   items = (const int*)d_in[9];
    float*       out   = (float*)d_out;

    (void)in_sizes; (void)n_in; (void)out_size;

    k_zero_deg<<<(NN + 255) / 256, 256>>>();
    k_deg<<<(NE + 255) / 256, 256>>>(ue, ie);
    k_part<<<NPART, 256>>>();
    k_scanpart<<<1, 1024>>>();
    k_off<<<NPART, 256>>>();
    k_scatter<<<(NE + 255) / 256, 256>>>(ue, ie);
    k_init<<<(NN * EMB / 4 + 255) / 256, 256>>>(Gu, Gi);

    k_prop<<<(NN * 32 + 255) / 256, 256>>>(0);   // x0 -> x1
    k_prop<<<(NN * 32 + 255) / 256, 256>>>(1);   // x1 -> x0
    k_prop<<<(NN * 32 + 255) / 256, 256>>>(0);   // x0 -> x1

    k_gemm<<<NB / 64, 256>>>(F, W, bias, items);
    k_score<<<(NB * 32 + 255) / 256, 256>>>(Tu, users, items, out);
}

// round 3
// speedup vs baseline: 1.5731x; 1.1255x over previous
#include <cuda_runtime.h>

#define NU   100000
#define NI   50000
#define NN   (NU + NI)          // 150000
#define EMB  64
#define NE   3000000            // edges per direction (total dir. edges = 2*NE)
#define FDIM 1024
#define NB   16384
#define NPART ((NN + 255) / 256)   // 586

// ---------------- static device scratch ----------------
__device__ float g_wa[(size_t)NN * EMB];   // w0, later w3
__device__ float g_wb[(size_t)NN * EMB];   // w1
__device__ float g_wc[(size_t)NN * EMB];   // w2
__device__ int   g_deg[NN];
__device__ int   g_off[NN];
__device__ int   g_cur[NN];
__device__ float g_dinv[NN];
__device__ int   g_part[1024];
__device__ int   g_csr[(size_t)2 * NE];    // src index only
__device__ float g_proj[(size_t)NB * EMB];

// ---------------- graph build ----------------
__global__ void k_zero_deg() {
    int n = blockIdx.x * blockDim.x + threadIdx.x;
    if (n < NN) g_deg[n] = 0;
}

__global__ void k_deg(const int* __restrict__ ue, const int* __restrict__ ie) {
    int e = blockIdx.x * blockDim.x + threadIdx.x;
    if (e < NE) {
        atomicAdd(&g_deg[ue[e]], 1);
        atomicAdd(&g_deg[ie[e] + NU], 1);
    }
}

// phase A: per-block sum of degrees (also computes dinv)
__global__ void __launch_bounds__(256) k_part() {
    __shared__ int s[256];
    int t = threadIdx.x;
    int n = blockIdx.x * 256 + t;
    int d = (n < NN) ? g_deg[n] : 0;
    if (n < NN) g_dinv[n] = (d > 0) ? rsqrtf((float)d) : 0.0f;
    s[t] = d;
    __syncthreads();
    #pragma unroll
    for (int o = 128; o > 0; o >>= 1) {
        if (t < o) s[t] += s[t + o];
        __syncthreads();
    }
    if (t == 0) g_part[blockIdx.x] = s[0];
}

// phase B: single-block exclusive scan of the partials
__global__ void __launch_bounds__(1024) k_scanpart() {
    __shared__ int s[1024];
    int t = threadIdx.x;
    int v = (t < NPART) ? g_part[t] : 0;
    s[t] = v;
    __syncthreads();
    #pragma unroll
    for (int o = 1; o < 1024; o <<= 1) {
        int u = (t >= o) ? s[t - o] : 0;
        __syncthreads();
        s[t] += u;
        __syncthreads();
    }
    if (t < NPART) g_part[t] = s[t] - v;   // exclusive
}

// phase C: per-block local scan + partial base -> offsets
__global__ void __launch_bounds__(256) k_off() {
    __shared__ int s[256];
    int t = threadIdx.x;
    int n = blockIdx.x * 256 + t;
    int d = (n < NN) ? g_deg[n] : 0;
    s[t] = d;
    __syncthreads();
    #pragma unroll
    for (int o = 1; o < 256; o <<= 1) {
        int u = (t >= o) ? s[t - o] : 0;
        __syncthreads();
        s[t] += u;
        __syncthreads();
    }
    if (n < NN) {
        int off = g_part[blockIdx.x] + s[t] - d;
        g_off[n] = off;
        g_cur[n] = off;
    }
}

__global__ void k_scatter(const int* __restrict__ ue, const int* __restrict__ ie) {
    int e = blockIdx.x * blockDim.x + threadIdx.x;
    if (e < NE) {
        int u  = ue[e];
        int it = ie[e] + NU;
        int p1 = atomicAdd(&g_cur[it], 1);
        g_csr[p1] = u;
        int p2 = atomicAdd(&g_cur[u], 1);
        g_csr[p2] = it;
    }
}

// w0 = dinv * x0
__global__ void k_init(const float* __restrict__ Gu, const float* __restrict__ Gi) {
    int i = blockIdx.x * blockDim.x + threadIdx.x;
    if (i < NN * EMB / 4) {
        int node = i >> 4;   // EMB/4 = 16 float4 per node
        const float4* src = (node < NU) ? (const float4*)Gu
                                        : (const float4*)Gi - (size_t)NU * 16;
        float4 v = src[i];
        float d = g_dinv[node];
        v.x *= d; v.y *= d; v.z *= d; v.w *= d;
        ((float4*)g_wa)[i] = v;
    }
}

// ---------------- propagation: one warp per dst node, pure gather-sum ----------------
// sel: 0: wa->wb, 1: wb->wc, 2: wc->wa
__global__ void __launch_bounds__(256) k_prop(int sel) {
    const float2* __restrict__ xin;
    float2* __restrict__ xout;
    if (sel == 0)      { xin = (const float2*)g_wa; xout = (float2*)g_wb; }
    else if (sel == 1) { xin = (const float2*)g_wb; xout = (float2*)g_wc; }
    else               { xin = (const float2*)g_wc; xout = (float2*)g_wa; }

    int w    = (blockIdx.x * blockDim.x + threadIdx.x) >> 5;
    int lane = threadIdx.x & 31;
    if (w >= NN) return;

    int cnt = g_deg[w];
    int off = g_off[w];
    const int* __restrict__ csr = g_csr + off;

    float s0 = 0.0f, s1 = 0.0f;
    int i = 0;
    // head until 16B aligned
    while (i < cnt && (((size_t)(csr + i)) & 15)) {
        int r0 = csr[i++];
        float2 v = xin[(size_t)r0 * 32 + lane];
        s0 += v.x; s1 += v.y;
    }
    for (; i + 4 <= cnt; i += 4) {
        int4 r = *(const int4*)(csr + i);
        float2 v0 = xin[(size_t)r.x * 32 + lane];
        float2 v1 = xin[(size_t)r.y * 32 + lane];
        float2 v2 = xin[(size_t)r.z * 32 + lane];
        float2 v3 = xin[(size_t)r.w * 32 + lane];
        s0 += v0.x; s1 += v0.y;
        s0 += v1.x; s1 += v1.y;
        s0 += v2.x; s1 += v2.y;
        s0 += v3.x; s1 += v3.y;
    }
    for (; i < cnt; i++) {
        int r0 = csr[i];
        float2 v = xin[(size_t)r0 * 32 + lane];
        s0 += v.x; s1 += v.y;
    }

    float d  = g_dinv[w];
    float d2 = d * d;
    float2 r; r.x = s0 * d2; r.y = s1 * d2;
    xout[(size_t)w * 32 + lane] = r;
}

// ---------------- projection GEMM: proj = F[items] @ W^T + b ----------------
__global__ void __launch_bounds__(256) k_gemm(const float* __restrict__ F,
                                              const float* __restrict__ W,
                                              const float* __restrict__ bias,
                                              const int* __restrict__ items) {
    __shared__ float Fs[64][33];
    __shared__ float Ws[32][65];
    __shared__ int   si[64];

    int t    = threadIdx.x;
    int base = blockIdx.x * 64;
    if (t < 64) si[t] = items[base + t];
    __syncthreads();

    int tx = t & 15;
    int ty = t >> 4;
    float acc[4][4] = {};

    for (int f0 = 0; f0 < FDIM; f0 += 32) {
        #pragma unroll
        for (int j = 0; j < 8; j++) {
            int idx = j * 256 + t;
            int row = idx >> 5, col = idx & 31;
            Fs[row][col] = F[(size_t)si[row] * FDIM + f0 + col];
        }
        #pragma unroll
        for (int j = 0; j < 8; j++) {
            int idx = j * 256 + t;
            int k = idx >> 5, c = idx & 31;
            Ws[c][k] = W[(size_t)k * FDIM + f0 + c];
        }
        __syncthreads();
        #pragma unroll
        for (int c = 0; c < 32; c++) {
            float fv[4], wv[4];
            #pragma unroll
            for (int ii = 0; ii < 4; ii++) fv[ii] = Fs[ty + 16 * ii][c];
            #pragma unroll
            for (int jj = 0; jj < 4; jj++) wv[jj] = Ws[c][tx + 16 * jj];
            #pragma unroll
            for (int ii = 0; ii < 4; ii++)
                #pragma unroll
                for (int jj = 0; jj < 4; jj++)
                    acc[ii][jj] = fmaf(fv[ii], wv[jj], acc[ii][jj]);
        }
        __syncthreads();
    }

    #pragma unroll
    for (int ii = 0; ii < 4; ii++) {
        int r = ty + 16 * ii;
        #pragma unroll
        for (int jj = 0; jj < 4; jj++) {
            int k = tx + 16 * jj;
            g_proj[(size_t)(base + r) * EMB + k] = acc[ii][jj] + bias[k];
        }
    }
}

// ---------------- final scoring: one warp per batch element ----------------
// acc[n] = 0.25*(x0[n] + sqrt(deg[n])*(w1[n]+w2[n]+w3[n]))
__global__ void __launch_bounds__(256) k_score(const float* __restrict__ Gu,
                                               const float* __restrict__ Gi,
                                               const float* __restrict__ Tu,
                                               const int* __restrict__ users,
                                               const int* __restrict__ items,
                                               float* __restrict__ out) {
    int w    = (blockIdx.x * blockDim.x + threadIdx.x) >> 5;
    int lane = threadIdx.x & 31;
    if (w >= NB) return;

    int u  = users[w];
    int it = items[w];
    int ni = NU + it;

    const float2* w1 = (const float2*)g_wb;
    const float2* w2 = (const float2*)g_wc;
    const float2* w3 = (const float2*)g_wa;

    size_t ou = (size_t)u * 32 + lane;
    size_t oi = (size_t)ni * 32 + lane;

    float sdu = sqrtf((float)g_deg[u]);
    float sdi = sqrtf((float)g_deg[ni]);

    float2 x0u = ((const float2*)Gu)[ou];
    float2 x0i = ((const float2*)Gi)[(size_t)it * 32 + lane];
    float2 a1 = w1[ou], a2 = w2[ou], a3 = w3[ou];
    float2 b1 = w1[oi], b2 = w2[oi], b3 = w3[oi];

    float gu0 = 0.25f * (x0u.x + sdu * (a1.x + a2.x + a3.x));
    float gu1 = 0.25f * (x0u.y + sdu * (a1.y + a2.y + a3.y));
    float gi0 = 0.25f * (x0i.x + sdi * (b1.x + b2.x + b3.x));
    float gi1 = 0.25f * (x0i.y + sdi * (b1.y + b2.y + b3.y));

    float2 pv = ((const float2*)g_proj)[(size_t)w * 32 + lane];
    float2 tv = ((const float2*)Tu)[ou];

    float d1 = gu0 * gi0 + gu1 * gi1;
    float ss = pv.x * pv.x + pv.y * pv.y;
    float d2 = tv.x * pv.x + tv.y * pv.y;

    #pragma unroll
    for (int o = 16; o > 0; o >>= 1) {
        d1 += __shfl_xor_sync(0xffffffffu, d1, o);
        ss += __shfl_xor_sync(0xffffffffu, ss, o);
        d2 += __shfl_xor_sync(0xffffffffu, d2, o);
    }
    if (lane == 0) {
        float inv = 1.0f / fmaxf(sqrtf(ss), 1e-12f);
        out[w] = d1 + d2 * inv;
    }
}

// ---------------- launch ----------------
extern "C" void kernel_launch(void* const* d_in, const int* in_sizes, int n_in,
                              void* d_out, int out_size) {
    const float* Gu    = (const float*)d_in[0];
    const float* Gi    = (const float*)d_in[1];
    const float* Tu    = (const float*)d_in[2];
    const float* F     = (const float*)d_in[3];
    const float* W     = (const float*)d_in[4];
    const float* bias  = (const float*)d_in[5];
    const int*   ue    = (const int*)d_in[6];
    const int*   ie    = (const int*)d_in[7];
    const int*   users = (const int*)d_in[8];
    const int*   items = (const int*)d_in[9];
    float*       out   = (float*)d_out;

    (void)in_sizes; (void)n_in; (void)out_size;

    k_zero_deg<<<(NN + 255) / 256, 256>>>();
    k_deg<<<(NE + 255) / 256, 256>>>(ue, ie);
    k_part<<<NPART, 256>>>();
    k_scanpart<<<1, 1024>>>();
    k_off<<<NPART, 256>>>();
    k_scatter<<<(NE + 255) / 256, 256>>>(ue, ie);
    k_init<<<(NN * EMB / 4 + 255) / 256, 256>>>(Gu, Gi);

    k_prop<<<(NN * 32 + 255) / 256, 256>>>(0);   // wa -> wb  (w1)
    k_prop<<<(NN * 32 + 255) / 256, 256>>>(1);   // wb -> wc  (w2)
    k_prop<<<(NN * 32 + 255) / 256, 256>>>(2);   // wc -> wa  (w3)

    k_gemm<<<NB / 64, 256>>>(F, W, bias, items);
    k_score<<<(NB * 32 + 255) / 256, 256>>>(Gu, Gi, Tu, users, items, out);
}

// round 6
// speedup vs baseline: 1.7626x; 1.1205x over previous
#include <cuda_runtime.h>

#define NU   100000
#define NI   50000
#define NN   (NU + NI)          // 150000
#define EMB  64
#define NE   3000000            // edges per direction (total dir. edges = 2*NE)
#define FDIM 1024
#define NB   16384
#define NPART ((NN + 255) / 256)   // 586

// ---------------- static device scratch ----------------
__device__ float g_wa[(size_t)NN * EMB];   // w0, later w3
__device__ float g_wb[(size_t)NN * EMB];   // w1
__device__ float g_wc[(size_t)NN * EMB];   // w2
__device__ int   g_deg[NN];
__device__ int   g_off[NN];
__device__ int   g_cur[NN];
__device__ float g_dinv[NN];
__device__ unsigned char g_flag[NN];
__device__ int   g_part[1024];
__device__ int   g_csr[(size_t)2 * NE];    // src index only
__device__ float g_proj[(size_t)NB * EMB];

// ---------------- graph build ----------------
__global__ void k_zero() {
    int n = blockIdx.x * blockDim.x + threadIdx.x;
    if (n < NN) { g_deg[n] = 0; g_flag[n] = 0; }
}

__global__ void k_mark(const int* __restrict__ users, const int* __restrict__ items) {
    int i = blockIdx.x * blockDim.x + threadIdx.x;
    if (i < NB) {
        g_flag[users[i]] = 1;
        g_flag[NU + items[i]] = 1;
    }
}

__global__ void k_deg(const int* __restrict__ ue, const int* __restrict__ ie) {
    int e = blockIdx.x * blockDim.x + threadIdx.x;
    if (e < NE) {
        atomicAdd(&g_deg[ue[e]], 1);
        atomicAdd(&g_deg[ie[e] + NU], 1);
    }
}

// phase A: per-block sum of degrees (also computes dinv)
__global__ void __launch_bounds__(256) k_part() {
    __shared__ int s[256];
    int t = threadIdx.x;
    int n = blockIdx.x * 256 + t;
    int d = (n < NN) ? g_deg[n] : 0;
    if (n < NN) g_dinv[n] = (d > 0) ? rsqrtf((float)d) : 0.0f;
    s[t] = d;
    __syncthreads();
    #pragma unroll
    for (int o = 128; o > 0; o >>= 1) {
        if (t < o) s[t] += s[t + o];
        __syncthreads();
    }
    if (t == 0) g_part[blockIdx.x] = s[0];
}

// phase B: single-block exclusive scan of the partials
__global__ void __launch_bounds__(1024) k_scanpart() {
    __shared__ int s[1024];
    int t = threadIdx.x;
    int v = (t < NPART) ? g_part[t] : 0;
    s[t] = v;
    __syncthreads();
    #pragma unroll
    for (int o = 1; o < 1024; o <<= 1) {
        int u = (t >= o) ? s[t - o] : 0;
        __syncthreads();
        s[t] += u;
        __syncthreads();
    }
    if (t < NPART) g_part[t] = s[t] - v;   // exclusive
}

// phase C: per-block local scan + partial base -> offsets
__global__ void __launch_bounds__(256) k_off() {
    __shared__ int s[256];
    int t = threadIdx.x;
    int n = blockIdx.x * 256 + t;
    int d = (n < NN) ? g_deg[n] : 0;
    s[t] = d;
    __syncthreads();
    #pragma unroll
    for (int o = 1; o < 256; o <<= 1) {
        int u = (t >= o) ? s[t - o] : 0;
        __syncthreads();
        s[t] += u;
        __syncthreads();
    }
    if (n < NN) {
        int off = g_part[blockIdx.x] + s[t] - d;
        g_off[n] = off;
        g_cur[n] = off;
    }
}

__global__ void k_scatter(const int* __restrict__ ue, const int* __restrict__ ie) {
    int e = blockIdx.x * blockDim.x + threadIdx.x;
    if (e < NE) {
        int u  = ue[e];
        int it = ie[e] + NU;
        int p1 = atomicAdd(&g_cur[it], 1);
        g_csr[p1] = u;
        int p2 = atomicAdd(&g_cur[u], 1);
        g_csr[p2] = it;
    }
}

// w0 = dinv * x0
__global__ void k_init(const float* __restrict__ Gu, const float* __restrict__ Gi) {
    int i = blockIdx.x * blockDim.x + threadIdx.x;
    if (i < NN * EMB / 4) {
        int node = i >> 4;   // EMB/4 = 16 float4 per node
        const float4* src = (node < NU) ? (const float4*)Gu
                                        : (const float4*)Gi - (size_t)NU * 16;
        float4 v = src[i];
        float d = g_dinv[node];
        v.x *= d; v.y *= d; v.z *= d; v.w *= d;
        ((float4*)g_wa)[i] = v;
    }
}

// ---------------- propagation: one warp per dst node, pure gather-sum ----------------
// sel: 0: wa->wb, 1: wb->wc, 2: wc->wa (pruned to flagged nodes)
__global__ void __launch_bounds__(256) k_prop(int sel, int pruned) {
    const float2* __restrict__ xin;
    float2* __restrict__ xout;
    if (sel == 0)      { xin = (const float2*)g_wa; xout = (float2*)g_wb; }
    else if (sel == 1) { xin = (const float2*)g_wb; xout = (float2*)g_wc; }
    else               { xin = (const float2*)g_wc; xout = (float2*)g_wa; }

    int w    = (blockIdx.x * blockDim.x + threadIdx.x) >> 5;
    int lane = threadIdx.x & 31;
    if (w >= NN) return;
    if (pruned && !g_flag[w]) return;

    int cnt = g_deg[w];
    const int* __restrict__ csr = g_csr + g_off[w];

    float s0 = 0.0f, s1 = 0.0f;
    int i = 0;
    // head until 16B aligned
    while (i < cnt && (((size_t)(csr + i)) & 15)) {
        int r0 = csr[i++];
        float2 v = xin[(size_t)r0 * 32 + lane];
        s0 += v.x; s1 += v.y;
    }
    for (; i + 8 <= cnt; i += 8) {
        int4 ra = *(const int4*)(csr + i);
        int4 rb = *(const int4*)(csr + i + 4);
        float2 v0 = xin[(size_t)ra.x * 32 + lane];
        float2 v1 = xin[(size_t)ra.y * 32 + lane];
        float2 v2 = xin[(size_t)ra.z * 32 + lane];
        float2 v3 = xin[(size_t)ra.w * 32 + lane];
        float2 v4 = xin[(size_t)rb.x * 32 + lane];
        float2 v5 = xin[(size_t)rb.y * 32 + lane];
        float2 v6 = xin[(size_t)rb.z * 32 + lane];
        float2 v7 = xin[(size_t)rb.w * 32 + lane];
        s0 += v0.x + v1.x + v2.x + v3.x;
        s1 += v0.y + v1.y + v2.y + v3.y;
        s0 += v4.x + v5.x + v6.x + v7.x;
        s1 += v4.y + v5.y + v6.y + v7.y;
    }
    for (; i + 4 <= cnt; i += 4) {
        int4 r = *(const int4*)(csr + i);
        float2 v0 = xin[(size_t)r.x * 32 + lane];
        float2 v1 = xin[(size_t)r.y * 32 + lane];
        float2 v2 = xin[(size_t)r.z * 32 + lane];
        float2 v3 = xin[(size_t)r.w * 32 + lane];
        s0 += v0.x + v1.x + v2.x + v3.x;
        s1 += v0.y + v1.y + v2.y + v3.y;
    }
    for (; i < cnt; i++) {
        int r0 = csr[i];
        float2 v = xin[(size_t)r0 * 32 + lane];
        s0 += v.x; s1 += v.y;
    }

    float d  = g_dinv[w];
    float d2 = d * d;
    float2 r; r.x = s0 * d2; r.y = s1 * d2;
    xout[(size_t)w * 32 + lane] = r;
}

// ---------------- projection GEMM: proj = F[items] @ W^T + b ----------------
__global__ void __launch_bounds__(256) k_gemm(const float* __restrict__ F,
                                              const float* __restrict__ W,
                                              const float* __restrict__ bias,
                                              const int* __restrict__ items) {
    __shared__ float Fs[64][33];
    __shared__ float Ws[32][65];
    __shared__ int   si[64];

    int t    = threadIdx.x;
    int base = blockIdx.x * 64;
    if (t < 64) si[t] = items[base + t];
    __syncthreads();

    int tx = t & 15;
    int ty = t >> 4;
    float acc[4][4] = {};

    for (int f0 = 0; f0 < FDIM; f0 += 32) {
        #pragma unroll
        for (int j = 0; j < 8; j++) {
            int idx = j * 256 + t;
            int row = idx >> 5, col = idx & 31;
            Fs[row][col] = F[(size_t)si[row] * FDIM + f0 + col];
        }
        #pragma unroll
        for (int j = 0; j < 8; j++) {
            int idx = j * 256 + t;
            int k = idx >> 5, c = idx & 31;
            Ws[c][k] = W[(size_t)k * FDIM + f0 + c];
        }
        __syncthreads();
        #pragma unroll
        for (int c = 0; c < 32; c++) {
            float fv[4], wv[4];
            #pragma unroll
            for (int ii = 0; ii < 4; ii++) fv[ii] = Fs[ty + 16 * ii][c];
            #pragma unroll
            for (int jj = 0; jj < 4; jj++) wv[jj] = Ws[c][tx + 16 * jj];
            #pragma unroll
            for (int ii = 0; ii < 4; ii++)
                #pragma unroll
                for (int jj = 0; jj < 4; jj++)
                    acc[ii][jj] = fmaf(fv[ii], wv[jj], acc[ii][jj]);
        }
        __syncthreads();
    }

    #pragma unroll
    for (int ii = 0; ii < 4; ii++) {
        int r = ty + 16 * ii;
        #pragma unroll
        for (int jj = 0; jj < 4; jj++) {
            int k = tx + 16 * jj;
            g_proj[(size_t)(base + r) * EMB + k] = acc[ii][jj] + bias[k];
        }
    }
}

// ---------------- final scoring: one warp per batch element ----------------
// acc[n] = 0.25*(x0[n] + sqrt(deg[n])*(w1[n]+w2[n]+w3[n]))
__global__ void __launch_bounds__(256) k_score(const float* __restrict__ Gu,
                                               const float* __restrict__ Gi,
                                               const float* __restrict__ Tu,
                                               const int* __restrict__ users,
                                               const int* __restrict__ items,
                                               float* __restrict__ out) {
    int w    = (blockIdx.x * blockDim.x + threadIdx.x) >> 5;
    int lane = threadIdx.x & 31;
    if (w >= NB) return;

    int u  = users[w];
    int it = items[w];
    int ni = NU + it;

    const float2* w1 = (const float2*)g_wb;
    const float2* w2 = (const float2*)g_wc;
    const float2* w3 = (const float2*)g_wa;

    size_t ou = (size_t)u * 32 + lane;
    size_t oi = (size_t)ni * 32 + lane;

    float sdu = sqrtf((float)g_deg[u]);
    float sdi = sqrtf((float)g_deg[ni]);

    float2 x0u = ((const float2*)Gu)[ou];
    float2 x0i = ((const float2*)Gi)[(size_t)it * 32 + lane];
    float2 a1 = w1[ou], a2 = w2[ou], a3 = w3[ou];
    float2 b1 = w1[oi], b2 = w2[oi], b3 = w3[oi];

    float gu0 = 0.25f * (x0u.x + sdu * (a1.x + a2.x + a3.x));
    float gu1 = 0.25f * (x0u.y + sdu * (a1.y + a2.y + a3.y));
    float gi0 = 0.25f * (x0i.x + sdi * (b1.x + b2.x + b3.x));
    float gi1 = 0.25f * (x0i.y + sdi * (b1.y + b2.y + b3.y));

    float2 pv = ((const float2*)g_proj)[(size_t)w * 32 + lane];
    float2 tv = ((const float2*)Tu)[ou];

    float d1 = gu0 * gi0 + gu1 * gi1;
    float ss = pv.x * pv.x + pv.y * pv.y;
    float d2 = tv.x * pv.x + tv.y * pv.y;

    #pragma unroll
    for (int o = 16; o > 0; o >>= 1) {
        d1 += __shfl_xor_sync(0xffffffffu, d1, o);
        ss += __shfl_xor_sync(0xffffffffu, ss, o);
        d2 += __shfl_xor_sync(0xffffffffu, d2, o);
    }
    if (lane == 0) {
        float inv = 1.0f / fmaxf(sqrtf(ss), 1e-12f);
        out[w] = d1 + d2 * inv;
    }
}

// ---------------- launch ----------------
extern "C" void kernel_launch(void* const* d_in, const int* in_sizes, int n_in,
                              void* d_out, int out_size) {
    const float* Gu    = (const float*)d_in[0];
    const float* Gi    = (const float*)d_in[1];
    const float* Tu    = (const float*)d_in[2];
    const float* F     = (const float*)d_in[3];
    const float* W     = (const float*)d_in[4];
    const float* bias  = (const float*)d_in[5];
    const int*   ue    = (const int*)d_in[6];
    const int*   ie    = (const int*)d_in[7];
    const int*   users = (const int*)d_in[8];
    const int*   items = (const int*)d_in[9];
    float*       out   = (float*)d_out;

    (void)in_sizes; (void)n_in; (void)out_size;

    k_zero<<<(NN + 255) / 256, 256>>>();
    k_mark<<<(NB + 255) / 256, 256>>>(users, items);
    k_deg<<<(NE + 255) / 256, 256>>>(ue, ie);
    k_part<<<NPART, 256>>>();
    k_scanpart<<<1, 1024>>>();
    k_off<<<NPART, 256>>>();
    k_scatter<<<(NE + 255) / 256, 256>>>(ue, ie);
    k_init<<<(NN * EMB / 4 + 255) / 256, 256>>>(Gu, Gi);

    k_prop<<<(NN * 32 + 255) / 256, 256>>>(0, 0);   // wa -> wb  (w1, all nodes)
    k_prop<<<(NN * 32 + 255) / 256, 256>>>(1, 0);   // wb -> wc  (w2, all nodes)
    k_prop<<<(NN * 32 + 255) / 256, 256>>>(2, 1);   // wc -> wa  (w3, batch nodes only)

    k_gemm<<<NB / 64, 256>>>(F, W, bias, items);
    k_score<<<(NB * 32 + 255) / 256, 256>>>(Gu, Gi, Tu, users, items, out);
}

// round 9
// speedup vs baseline: 1.7957x; 1.0187x over previous
#include <cuda_runtime.h>
#include <cuda_fp16.h>

#define NU   100000
#define NI   50000
#define NN   (NU + NI)          // 150000
#define EMB  64
#define NE   3000000            // edges per direction (total dir. edges = 2*NE)
#define FDIM 1024
#define NB   16384
#define NPART ((NN + 255) / 256)   // 586

// ---------------- static device scratch ----------------
__device__ __half g_wa[(size_t)NN * EMB];   // w0, later w3
__device__ __half g_wb[(size_t)NN * EMB];   // w1
__device__ __half g_wc[(size_t)NN * EMB];   // w2
__device__ int   g_deg[NN];
__device__ int   g_off[NN];
__device__ int   g_cur[NN];
__device__ float g_dinv[NN];
__device__ unsigned char g_flag[NN];
__device__ int   g_part[1024];
__device__ int   g_csr[(size_t)2 * NE];    // src index only
__device__ float g_proj[(size_t)NB * EMB];

// ---------------- graph build ----------------
__global__ void k_zero() {
    int n = blockIdx.x * blockDim.x + threadIdx.x;
    if (n < NN) { g_deg[n] = 0; g_flag[n] = 0; }
}

__global__ void k_mark(const int* __restrict__ users, const int* __restrict__ items) {
    int i = blockIdx.x * blockDim.x + threadIdx.x;
    if (i < NB) {
        g_flag[users[i]] = 1;
        g_flag[NU + items[i]] = 1;
    }
}

__global__ void k_deg(const int* __restrict__ ue, const int* __restrict__ ie) {
    int e = blockIdx.x * blockDim.x + threadIdx.x;
    if (e < NE) {
        atomicAdd(&g_deg[ue[e]], 1);
        atomicAdd(&g_deg[ie[e] + NU], 1);
    }
}

// phase A: per-block sum of degrees (also computes dinv)
__global__ void __launch_bounds__(256) k_part() {
    __shared__ int s[256];
    int t = threadIdx.x;
    int n = blockIdx.x * 256 + t;
    int d = (n < NN) ? g_deg[n] : 0;
    if (n < NN) g_dinv[n] = (d > 0) ? rsqrtf((float)d) : 0.0f;
    s[t] = d;
    __syncthreads();
    #pragma unroll
    for (int o = 128; o > 0; o >>= 1) {
        if (t < o) s[t] += s[t + o];
        __syncthreads();
    }
    if (t == 0) g_part[blockIdx.x] = s[0];
}

// phase B: single-block exclusive scan of the partials
__global__ void __launch_bounds__(1024) k_scanpart() {
    __shared__ int s[1024];
    int t = threadIdx.x;
    int v = (t < NPART) ? g_part[t] : 0;
    s[t] = v;
    __syncthreads();
    #pragma unroll
    for (int o = 1; o < 1024; o <<= 1) {
        int u = (t >= o) ? s[t - o] : 0;
        __syncthreads();
        s[t] += u;
        __syncthreads();
    }
    if (t < NPART) g_part[t] = s[t] - v;   // exclusive
}

// phase C: per-block local scan + partial base -> offsets
__global__ void __launch_bounds__(256) k_off() {
    __shared__ int s[256];
    int t = threadIdx.x;
    int n = blockIdx.x * 256 + t;
    int d = (n < NN) ? g_deg[n] : 0;
    s[t] = d;
    __syncthreads();
    #pragma unroll
    for (int o = 1; o < 256; o <<= 1) {
        int u = (t >= o) ? s[t - o] : 0;
        __syncthreads();
        s[t] += u;
        __syncthreads();
    }
    if (n < NN) {
        int off = g_part[blockIdx.x] + s[t] - d;
        g_off[n] = off;
        g_cur[n] = off;
    }
}

__global__ void k_scatter(const int* __restrict__ ue, const int* __restrict__ ie) {
    int e = blockIdx.x * blockDim.x + threadIdx.x;
    if (e < NE) {
        int u  = ue[e];
        int it = ie[e] + NU;
        int p1 = atomicAdd(&g_cur[it], 1);
        g_csr[p1] = u;
        int p2 = atomicAdd(&g_cur[u], 1);
        g_csr[p2] = it;
    }
}

// w0 = fp16(dinv * x0)
__global__ void k_init(const float* __restrict__ Gu, const float* __restrict__ Gi) {
    int i = blockIdx.x * blockDim.x + threadIdx.x;
    if (i < NN * EMB / 4) {
        int node = i >> 4;   // EMB/4 = 16 float4 per node
        const float4* src = (node < NU) ? (const float4*)Gu
                                        : (const float4*)Gi - (size_t)NU * 16;
        float4 v = src[i];
        float d = g_dinv[node];
        __half2 h0 = __floats2half2_rn(v.x * d, v.y * d);
        __half2 h1 = __floats2half2_rn(v.z * d, v.w * d);
        ((__half2*)g_wa)[2 * i]     = h0;
        ((__half2*)g_wa)[2 * i + 1] = h1;
    }
}

// ---------------- propagation: one warp per dst node, fp16 gather, fp32 accumulate ----------------
// sel: 0: wa->wb, 1: wb->wc, 2: wc->wa (pruned to flagged nodes)
__global__ void __launch_bounds__(256) k_prop(int sel, int pruned) {
    const __half2* __restrict__ xin;
    __half2* __restrict__ xout;
    if (sel == 0)      { xin = (const __half2*)g_wa; xout = (__half2*)g_wb; }
    else if (sel == 1) { xin = (const __half2*)g_wb; xout = (__half2*)g_wc; }
    else               { xin = (const __half2*)g_wc; xout = (__half2*)g_wa; }

    int w    = (blockIdx.x * blockDim.x + threadIdx.x) >> 5;
    int lane = threadIdx.x & 31;
    if (w >= NN) return;
    if (pruned && !g_flag[w]) return;

    int cnt = g_deg[w];
    const int* __restrict__ csr = g_csr + g_off[w];

    float s0 = 0.0f, s1 = 0.0f;
    int i = 0;
    // head until 16B aligned
    while (i < cnt && (((size_t)(csr + i)) & 15)) {
        int r0 = csr[i++];
        float2 v = __half22float2(xin[(size_t)r0 * 32 + lane]);
        s0 += v.x; s1 += v.y;
    }
    for (; i + 8 <= cnt; i += 8) {
        int4 ra = *(const int4*)(csr + i);
        int4 rb = *(const int4*)(csr + i + 4);
        __half2 h0 = xin[(size_t)ra.x * 32 + lane];
        __half2 h1 = xin[(size_t)ra.y * 32 + lane];
        __half2 h2 = xin[(size_t)ra.z * 32 + lane];
        __half2 h3 = xin[(size_t)ra.w * 32 + lane];
        __half2 h4 = xin[(size_t)rb.x * 32 + lane];
        __half2 h5 = xin[(size_t)rb.y * 32 + lane];
        __half2 h6 = xin[(size_t)rb.z * 32 + lane];
        __half2 h7 = xin[(size_t)rb.w * 32 + lane];
        float2 v0 = __half22float2(h0), v1 = __half22float2(h1);
        float2 v2 = __half22float2(h2), v3 = __half22float2(h3);
        float2 v4 = __half22float2(h4), v5 = __half22float2(h5);
        float2 v6 = __half22float2(h6), v7 = __half22float2(h7);
        s0 += v0.x + v1.x + v2.x + v3.x;
        s1 += v0.y + v1.y + v2.y + v3.y;
        s0 += v4.x + v5.x + v6.x + v7.x;
        s1 += v4.y + v5.y + v6.y + v7.y;
    }
    for (; i + 4 <= cnt; i += 4) {
        int4 r = *(const int4*)(csr + i);
        float2 v0 = __half22float2(xin[(size_t)r.x * 32 + lane]);
        float2 v1 = __half22float2(xin[(size_t)r.y * 32 + lane]);
        float2 v2 = __half22float2(xin[(size_t)r.z * 32 + lane]);
        float2 v3 = __half22float2(xin[(size_t)r.w * 32 + lane]);
        s0 += v0.x + v1.x + v2.x + v3.x;
        s1 += v0.y + v1.y + v2.y + v3.y;
    }
    for (; i < cnt; i++) {
        int r0 = csr[i];
        float2 v = __half22float2(xin[(size_t)r0 * 32 + lane]);
        s0 += v.x; s1 += v.y;
    }

    float d  = g_dinv[w];
    float d2 = d * d;
    xout[(size_t)w * 32 + lane] = __floats2half2_rn(s0 * d2, s1 * d2);
}

// ---------------- projection GEMM: proj = F[items] @ W^T + b ----------------
__global__ void __launch_bounds__(256) k_gemm(const float* __restrict__ F,
                                              const float* __restrict__ W,
                                              const float* __restrict__ bias,
                                              const int* __restrict__ items) {
    __shared__ float Fs[64][33];
    __shared__ float Ws[32][65];
    __shared__ int   si[64];

    int t    = threadIdx.x;
    int base = blockIdx.x * 64;
    if (t < 64) si[t] = items[base + t];
    __syncthreads();

    int tx = t & 15;
    int ty = t >> 4;
    float acc[4][4] = {};

    for (int f0 = 0; f0 < FDIM; f0 += 32) {
        #pragma unroll
        for (int j = 0; j < 8; j++) {
            int idx = j * 256 + t;
            int row = idx >> 5, col = idx & 31;
            Fs[row][col] = F[(size_t)si[row] * FDIM + f0 + col];
        }
        #pragma unroll
        for (int j = 0; j < 8; j++) {
            int idx = j * 256 + t;
            int k = idx >> 5, c = idx & 31;
            Ws[c][k] = W[(size_t)k * FDIM + f0 + c];
        }
        __syncthreads();
        #pragma unroll
        for (int c = 0; c < 32; c++) {
            float fv[4], wv[4];
            #pragma unroll
            for (int ii = 0; ii < 4; ii++) fv[ii] = Fs[ty + 16 * ii][c];
            #pragma unroll
            for (int jj = 0; jj < 4; jj++) wv[jj] = Ws[c][tx + 16 * jj];
            #pragma unroll
            for (int ii = 0; ii < 4; ii++)
                #pragma unroll
                for (int jj = 0; jj < 4; jj++)
                    acc[ii][jj] = fmaf(fv[ii], wv[jj], acc[ii][jj]);
        }
        __syncthreads();
    }

    #pragma unroll
    for (int ii = 0; ii < 4; ii++) {
        int r = ty + 16 * ii;
        #pragma unroll
        for (int jj = 0; jj < 4; jj++) {
            int k = tx + 16 * jj;
            g_proj[(size_t)(base + r) * EMB + k] = acc[ii][jj] + bias[k];
        }
    }
}

// ---------------- final scoring: one warp per batch element ----------------
// acc[n] = 0.25*(x0[n] + sqrt(deg[n])*(w1[n]+w2[n]+w3[n]))
__global__ void __launch_bounds__(256) k_score(const float* __restrict__ Gu,
                                               const float* __restrict__ Gi,
                                               const float* __restrict__ Tu,
                                               const int* __restrict__ users,
                                               const int* __restrict__ items,
                                               float* __restrict__ out) {
    int w    = (blockIdx.x * blockDim.x + threadIdx.x) >> 5;
    int lane = threadIdx.x & 31;
    if (w >= NB) return;

    int u  = users[w];
    int it = items[w];
    int ni = NU + it;

    const __half2* w1 = (const __half2*)g_wb;
    const __half2* w2 = (const __half2*)g_wc;
    const __half2* w3 = (const __half2*)g_wa;

    size_t ou = (size_t)u * 32 + lane;
    size_t oi = (size_t)ni * 32 + lane;

    float sdu = sqrtf((float)g_deg[u]);
    float sdi = sqrtf((float)g_deg[ni]);

    float2 x0u = ((const float2*)Gu)[ou];
    float2 x0i = ((const float2*)Gi)[(size_t)it * 32 + lane];
    float2 a1 = __half22float2(w1[ou]);
    float2 a2 = __half22float2(w2[ou]);
    float2 a3 = __half22float2(w3[ou]);
    float2 b1 = __half22float2(w1[oi]);
    float2 b2 = __half22float2(w2[oi]);
    float2 b3 = __half22float2(w3[oi]);

    float gu0 = 0.25f * (x0u.x + sdu * (a1.x + a2.x + a3.x));
    float gu1 = 0.25f * (x0u.y + sdu * (a1.y + a2.y + a3.y));
    float gi0 = 0.25f * (x0i.x + sdi * (b1.x + b2.x + b3.x));
    float gi1 = 0.25f * (x0i.y + sdi * (b1.y + b2.y + b3.y));

    float2 pv = ((const float2*)g_proj)[(size_t)w * 32 + lane];
    float2 tv = ((const float2*)Tu)[ou];

    float d1 = gu0 * gi0 + gu1 * gi1;
    float ss = pv.x * pv.x + pv.y * pv.y;
    float d2 = tv.x * pv.x + tv.y * pv.y;

    #pragma unroll
    for (int o = 16; o > 0; o >>= 1) {
        d1 += __shfl_xor_sync(0xffffffffu, d1, o);
        ss += __shfl_xor_sync(0xffffffffu, ss, o);
        d2 += __shfl_xor_sync(0xffffffffu, d2, o);
    }
    if (lane == 0) {
        float inv = 1.0f / fmaxf(sqrtf(ss), 1e-12f);
        out[w] = d1 + d2 * inv;
    }
}

// ---------------- launch ----------------
extern "C" void kernel_launch(void* const* d_in, const int* in_sizes, int n_in,
                              void* d_out, int out_size) {
    const float* Gu    = (const float*)d_in[0];
    const float* Gi    = (const float*)d_in[1];
    const float* Tu    = (const float*)d_in[2];
    const float* F     = (const float*)d_in[3];
    const float* W     = (const float*)d_in[4];
    const float* bias  = (const float*)d_in[5];
    const int*   ue    = (const int*)d_in[6];
    const int*   ie    = (const int*)d_in[7];
    const int*   users = (const int*)d_in[8];
    const int*   items = (const int*)d_in[9];
    float*       out   = (float*)d_out;

    (void)in_sizes; (void)n_in; (void)out_size;

    k_zero<<<(NN + 255) / 256, 256>>>();
    k_mark<<<(NB + 255) / 256, 256>>>(users, items);
    k_deg<<<(NE + 255) / 256, 256>>>(ue, ie);
    k_part<<<NPART, 256>>>();
    k_scanpart<<<1, 1024>>>();
    k_off<<<NPART, 256>>>();
    k_scatter<<<(NE + 255) / 256, 256>>>(ue, ie);
    k_init<<<(NN * EMB / 4 + 255) / 256, 256>>>(Gu, Gi);

    k_prop<<<(NN * 32 + 255) / 256, 256>>>(0, 0);   // wa -> wb  (w1, all nodes)
    k_prop<<<(NN * 32 + 255) / 256, 256>>>(1, 0);   // wb -> wc  (w2, all nodes)
    k_prop<<<(NN * 32 + 255) / 256, 256>>>(2, 1);   // wc -> wa  (w3, batch nodes only)

    k_gemm<<<NB / 64, 256>>>(F, W, bias, items);
    k_score<<<(NB * 32 + 255) / 256, 256>>>(Gu, Gi, Tu, users, items, out);
}

// round 10
// speedup vs baseline: 2.3727x; 1.3213x over previous
#include <cuda_runtime.h>
#include <cuda_fp16.h>
#include <cstdint>

#define NU   100000
#define NI   50000
#define NN   (NU + NI)          // 150000
#define EMB  64
#define NE   3000000            // edges per direction (total dir. edges = 2*NE)
#define FDIM 1024
#define NB   16384
#define NPART ((NN + 255) / 256)   // 586

// ---------------- static device scratch ----------------
__device__ __half g_wa[(size_t)NN * EMB];   // w0, later w3
__device__ __half g_wb[(size_t)NN * EMB];   // w1
__device__ __half g_wc[(size_t)NN * EMB];   // w2
__device__ int   g_deg[NN];
__device__ int   g_off[NN];
__device__ int   g_cur[NN];
__device__ float g_dinv[NN];
__device__ unsigned char g_flag[NN];
__device__ int   g_part[1024];
__device__ int   g_csr[(size_t)2 * NE];    // src index only
__device__ float g_proj[(size_t)NB * EMB];

// ---------------- graph build ----------------
__global__ void k_zero() {
    int n = blockIdx.x * blockDim.x + threadIdx.x;
    if (n < NN) { g_deg[n] = 0; g_flag[n] = 0; }
}

__global__ void k_mark(const int* __restrict__ users, const int* __restrict__ items) {
    int i = blockIdx.x * blockDim.x + threadIdx.x;
    if (i < NB) {
        g_flag[users[i]] = 1;
        g_flag[NU + items[i]] = 1;
    }
}

__global__ void k_deg(const int* __restrict__ ue, const int* __restrict__ ie) {
    int e = blockIdx.x * blockDim.x + threadIdx.x;
    if (e < NE) {
        atomicAdd(&g_deg[ue[e]], 1);
        atomicAdd(&g_deg[ie[e] + NU], 1);
    }
}

// phase A: per-block sum of degrees (also computes dinv)
__global__ void __launch_bounds__(256) k_part() {
    __shared__ int s[256];
    int t = threadIdx.x;
    int n = blockIdx.x * 256 + t;
    int d = (n < NN) ? g_deg[n] : 0;
    if (n < NN) g_dinv[n] = (d > 0) ? rsqrtf((float)d) : 0.0f;
    s[t] = d;
    __syncthreads();
    #pragma unroll
    for (int o = 128; o > 0; o >>= 1) {
        if (t < o) s[t] += s[t + o];
        __syncthreads();
    }
    if (t == 0) g_part[blockIdx.x] = s[0];
}

// phase B: single-block exclusive scan of the partials
__global__ void __launch_bounds__(1024) k_scanpart() {
    __shared__ int s[1024];
    int t = threadIdx.x;
    int v = (t < NPART) ? g_part[t] : 0;
    s[t] = v;
    __syncthreads();
    #pragma unroll
    for (int o = 1; o < 1024; o <<= 1) {
        int u = (t >= o) ? s[t - o] : 0;
        __syncthreads();
        s[t] += u;
        __syncthreads();
    }
    if (t < NPART) g_part[t] = s[t] - v;   // exclusive
}

// phase C: per-block local scan + partial base -> offsets
__global__ void __launch_bounds__(256) k_off() {
    __shared__ int s[256];
    int t = threadIdx.x;
    int n = blockIdx.x * 256 + t;
    int d = (n < NN) ? g_deg[n] : 0;
    s[t] = d;
    __syncthreads();
    #pragma unroll
    for (int o = 1; o < 256; o <<= 1) {
        int u = (t >= o) ? s[t - o] : 0;
        __syncthreads();
        s[t] += u;
        __syncthreads();
    }
    if (n < NN) {
        int off = g_part[blockIdx.x] + s[t] - d;
        g_off[n] = off;
        g_cur[n] = off;
    }
}

__global__ void k_scatter(const int* __restrict__ ue, const int* __restrict__ ie) {
    int e = blockIdx.x * blockDim.x + threadIdx.x;
    if (e < NE) {
        int u  = ue[e];
        int it = ie[e] + NU;
        int p1 = atomicAdd(&g_cur[it], 1);
        g_csr[p1] = u;
        int p2 = atomicAdd(&g_cur[u], 1);
        g_csr[p2] = it;
    }
}

// w0 = fp16(dinv * x0)
__global__ void k_init(const float* __restrict__ Gu, const float* __restrict__ Gi) {
    int i = blockIdx.x * blockDim.x + threadIdx.x;
    if (i < NN * EMB / 4) {
        int node = i >> 4;   // EMB/4 = 16 float4 per node
        const float4* src = (node < NU) ? (const float4*)Gu
                                        : (const float4*)Gi - (size_t)NU * 16;
        float4 v = src[i];
        float d = g_dinv[node];
        __half2 h0 = __floats2half2_rn(v.x * d, v.y * d);
        __half2 h1 = __floats2half2_rn(v.z * d, v.w * d);
        ((__half2*)g_wa)[2 * i]     = h0;
        ((__half2*)g_wa)[2 * i + 1] = h1;
    }
}

// ---------------- propagation: one warp per dst node, fp16 gather, fp32 accumulate ----------------
// sel: 0: wa->wb, 1: wb->wc, 2: wc->wa (pruned to flagged nodes)
__global__ void __launch_bounds__(256) k_prop(int sel, int pruned) {
    const __half2* __restrict__ xin;
    __half2* __restrict__ xout;
    if (sel == 0)      { xin = (const __half2*)g_wa; xout = (__half2*)g_wb; }
    else if (sel == 1) { xin = (const __half2*)g_wb; xout = (__half2*)g_wc; }
    else               { xin = (const __half2*)g_wc; xout = (__half2*)g_wa; }

    int w    = (blockIdx.x * blockDim.x + threadIdx.x) >> 5;
    int lane = threadIdx.x & 31;
    if (w >= NN) return;
    if (pruned && !g_flag[w]) return;

    int cnt = g_deg[w];
    const int* __restrict__ csr = g_csr + g_off[w];

    float s0 = 0.0f, s1 = 0.0f;
    int i = 0;
    // head until 16B aligned
    while (i < cnt && (((size_t)(csr + i)) & 15)) {
        int r0 = csr[i++];
        float2 v = __half22float2(xin[(size_t)r0 * 32 + lane]);
        s0 += v.x; s1 += v.y;
    }
    // 16-wide main loop: 4 index int4 loads + 16 gathers in flight
    for (; i + 16 <= cnt; i += 16) {
        int4 ra = *(const int4*)(csr + i);
        int4 rb = *(const int4*)(csr + i + 4);
        int4 rc = *(const int4*)(csr + i + 8);
        int4 rd = *(const int4*)(csr + i + 12);
        __half2 h0 = xin[(size_t)ra.x * 32 + lane];
        __half2 h1 = xin[(size_t)ra.y * 32 + lane];
        __half2 h2 = xin[(size_t)ra.z * 32 + lane];
        __half2 h3 = xin[(size_t)ra.w * 32 + lane];
        __half2 h4 = xin[(size_t)rb.x * 32 + lane];
        __half2 h5 = xin[(size_t)rb.y * 32 + lane];
        __half2 h6 = xin[(size_t)rb.z * 32 + lane];
        __half2 h7 = xin[(size_t)rb.w * 32 + lane];
        __half2 h8 = xin[(size_t)rc.x * 32 + lane];
        __half2 h9 = xin[(size_t)rc.y * 32 + lane];
        __half2 ha = xin[(size_t)rc.z * 32 + lane];
        __half2 hb = xin[(size_t)rc.w * 32 + lane];
        __half2 hc = xin[(size_t)rd.x * 32 + lane];
        __half2 hd = xin[(size_t)rd.y * 32 + lane];
        __half2 he = xin[(size_t)rd.z * 32 + lane];
        __half2 hf = xin[(size_t)rd.w * 32 + lane];
        float2 v0 = __half22float2(h0), v1 = __half22float2(h1);
        float2 v2 = __half22float2(h2), v3 = __half22float2(h3);
        float2 v4 = __half22float2(h4), v5 = __half22float2(h5);
        float2 v6 = __half22float2(h6), v7 = __half22float2(h7);
        float2 v8 = __half22float2(h8), v9 = __half22float2(h9);
        float2 va = __half22float2(ha), vb = __half22float2(hb);
        float2 vc = __half22float2(hc), vd = __half22float2(hd);
        float2 ve = __half22float2(he), vf = __half22float2(hf);
        s0 += v0.x + v1.x + v2.x + v3.x + v4.x + v5.x + v6.x + v7.x;
        s1 += v0.y + v1.y + v2.y + v3.y + v4.y + v5.y + v6.y + v7.y;
        s0 += v8.x + v9.x + va.x + vb.x + vc.x + vd.x + ve.x + vf.x;
        s1 += v8.y + v9.y + va.y + vb.y + vc.y + vd.y + ve.y + vf.y;
    }
    for (; i + 4 <= cnt; i += 4) {
        int4 r = *(const int4*)(csr + i);
        float2 v0 = __half22float2(xin[(size_t)r.x * 32 + lane]);
        float2 v1 = __half22float2(xin[(size_t)r.y * 32 + lane]);
        float2 v2 = __half22float2(xin[(size_t)r.z * 32 + lane]);
        float2 v3 = __half22float2(xin[(size_t)r.w * 32 + lane]);
        s0 += v0.x + v1.x + v2.x + v3.x;
        s1 += v0.y + v1.y + v2.y + v3.y;
    }
    for (; i < cnt; i++) {
        int r0 = csr[i];
        float2 v = __half22float2(xin[(size_t)r0 * 32 + lane]);
        s0 += v.x; s1 += v.y;
    }

    float d  = g_dinv[w];
    float d2 = d * d;
    xout[(size_t)w * 32 + lane] = __floats2half2_rn(s0 * d2, s1 * d2);
}

// ---------------- projection GEMM via tensor cores (fp16 hi/lo split, fp32 accum) ----------------
// proj = F[items] @ W^T + b, computed as Ahi*Bhi + Ahi*Blo + Alo*Bhi (lo*lo dropped, ~2^-22)
// block: 256 thr = 8 warps; tile 64 items x 64 out; warp (w&3): rows 16, (w>>2): n-half 32
#define MMA16816(C, A, B)                                                        \
    asm volatile("mma.sync.aligned.m16n8k16.row.col.f32.f16.f16.f32 "            \
                 "{%0,%1,%2,%3}, {%4,%5,%6,%7}, {%8,%9}, {%0,%1,%2,%3};"         \
                 : "+f"((C)[0]), "+f"((C)[1]), "+f"((C)[2]), "+f"((C)[3])        \
                 : "r"((A)[0]), "r"((A)[1]), "r"((A)[2]), "r"((A)[3]),           \
                   "r"((B)[0]), "r"((B)[1]))

__global__ void __launch_bounds__(256) k_gemm(const float* __restrict__ F,
                                              const float* __restrict__ W,
                                              const float* __restrict__ bias,
                                              const int* __restrict__ items) {
    __shared__ __half sFhi[64][40];
    __shared__ __half sFlo[64][40];
    __shared__ __half sWhi[64][40];
    __shared__ __half sWlo[64][40];
    __shared__ int si[64];

    int t    = threadIdx.x;
    int base = blockIdx.x * 64;
    if (t < 64) si[t] = items[base + t];
    __syncthreads();

    int warp = t >> 5, lane = t & 31;
    int g = lane >> 2, tc = lane & 3;
    int mr    = (warp & 3) * 16;
    int nbase = (warp >> 2) * 32;

    float acc[4][4];
    #pragma unroll
    for (int a = 0; a < 4; a++)
        #pragma unroll
        for (int b = 0; b < 4; b++) acc[a][b] = 0.0f;

    for (int k0 = 0; k0 < FDIM; k0 += 32) {
        // stage F and W k-tiles as hi/lo fp16 (each thread: 2 float4 of F, 2 of W)
        #pragma unroll
        for (int j = 0; j < 2; j++) {
            int idx = j * 256 + t;     // 0..511
            int row = idx >> 3;        // 8 float4 per 32-col row
            int c   = (idx & 7) * 4;
            float4 v = *(const float4*)(F + (size_t)si[row] * FDIM + k0 + c);
            __half h;
            h = __float2half_rn(v.x); sFhi[row][c+0] = h; sFlo[row][c+0] = __float2half_rn(v.x - __half2float(h));
            h = __float2half_rn(v.y); sFhi[row][c+1] = h; sFlo[row][c+1] = __float2half_rn(v.y - __half2float(h));
            h = __float2half_rn(v.z); sFhi[row][c+2] = h; sFlo[row][c+2] = __float2half_rn(v.z - __half2float(h));
            h = __float2half_rn(v.w); sFhi[row][c+3] = h; sFlo[row][c+3] = __float2half_rn(v.w - __half2float(h));
            float4 wv = *(const float4*)(W + (size_t)row * FDIM + k0 + c);
            h = __float2half_rn(wv.x); sWhi[row][c+0] = h; sWlo[row][c+0] = __float2half_rn(wv.x - __half2float(h));
            h = __float2half_rn(wv.y); sWhi[row][c+1] = h; sWlo[row][c+1] = __float2half_rn(wv.y - __half2float(h));
            h = __float2half_rn(wv.z); sWhi[row][c+2] = h; sWlo[row][c+2] = __float2half_rn(wv.z - __half2float(h));
            h = __float2half_rn(wv.w); sWhi[row][c+3] = h; sWlo[row][c+3] = __float2half_rn(wv.w - __half2float(h));
        }
        __syncthreads();

        #pragma unroll
        for (int ks = 0; ks < 2; ks++) {
            int kb = ks * 16;
            uint32_t ah[4], al[4];
            ah[0] = *(const uint32_t*)&sFhi[mr + g    ][kb + 2 * tc];
            ah[1] = *(const uint32_t*)&sFhi[mr + g + 8][kb + 2 * tc];
            ah[2] = *(const uint32_t*)&sFhi[mr + g    ][kb + 8 + 2 * tc];
            ah[3] = *(const uint32_t*)&sFhi[mr + g + 8][kb + 8 + 2 * tc];
            al[0] = *(const uint32_t*)&sFlo[mr + g    ][kb + 2 * tc];
            al[1] = *(const uint32_t*)&sFlo[mr + g + 8][kb + 2 * tc];
            al[2] = *(const uint32_t*)&sFlo[mr + g    ][kb + 8 + 2 * tc];
            al[3] = *(const uint32_t*)&sFlo[mr + g + 8][kb + 8 + 2 * tc];
            #pragma unroll
            for (int nt = 0; nt < 4; nt++) {
                int n0 = nbase + nt * 8;
                uint32_t bh[2], bl[2];
                bh[0] = *(const uint32_t*)&sWhi[n0 + g][kb + 2 * tc];
                bh[1] = *(const uint32_t*)&sWhi[n0 + g][kb + 8 + 2 * tc];
                bl[0] = *(const uint32_t*)&sWlo[n0 + g][kb + 2 * tc];
                bl[1] = *(const uint32_t*)&sWlo[n0 + g][kb + 8 + 2 * tc];
                MMA16816(acc[nt], ah, bh);
                MMA16816(acc[nt], ah, bl);
                MMA16816(acc[nt], al, bh);
            }
        }
        __syncthreads();
    }

    // epilogue: c0,c1 -> (row g, cols 2tc,2tc+1); c2,c3 -> (row g+8)
    #pragma unroll
    for (int nt = 0; nt < 4; nt++) {
        int c0 = nbase + nt * 8 + 2 * tc;
        int r0 = base + mr + g;
        g_proj[(size_t)r0 * EMB + c0]           = acc[nt][0] + bias[c0];
        g_proj[(size_t)r0 * EMB + c0 + 1]       = acc[nt][1] + bias[c0 + 1];
        g_proj[(size_t)(r0 + 8) * EMB + c0]     = acc[nt][2] + bias[c0];
        g_proj[(size_t)(r0 + 8) * EMB + c0 + 1] = acc[nt][3] + bias[c0 + 1];
    }
}

// ---------------- final scoring: one warp per batch element ----------------
// acc[n] = 0.25*(x0[n] + sqrt(deg[n])*(w1[n]+w2[n]+w3[n]))
__global__ void __launch_bounds__(256) k_score(const float* __restrict__ Gu,
                                               const float* __restrict__ Gi,
                                               const float* __restrict__ Tu,
                                               const int* __restrict__ users,
                                               const int* __restrict__ items,
                                               float* __restrict__ out) {
    int w    = (blockIdx.x * blockDim.x + threadIdx.x) >> 5;
    int lane = threadIdx.x & 31;
    if (w >= NB) return;

    int u  = users[w];
    int it = items[w];
    int ni = NU + it;

    const __half2* w1 = (const __half2*)g_wb;
    const __half2* w2 = (const __half2*)g_wc;
    const __half2* w3 = (const __half2*)g_wa;

    size_t ou = (size_t)u * 32 + lane;
    size_t oi = (size_t)ni * 32 + lane;

    float sdu = sqrtf((float)g_deg[u]);
    float sdi = sqrtf((float)g_deg[ni]);

    float2 x0u = ((const float2*)Gu)[ou];
    float2 x0i = ((const float2*)Gi)[(size_t)it * 32 + lane];
    float2 a1 = __half22float2(w1[ou]);
    float2 a2 = __half22float2(w2[ou]);
    float2 a3 = __half22float2(w3[ou]);
    float2 b1 = __half22float2(w1[oi]);
    float2 b2 = __half22float2(w2[oi]);
    float2 b3 = __half22float2(w3[oi]);

    float gu0 = 0.25f * (x0u.x + sdu * (a1.x + a2.x + a3.x));
    float gu1 = 0.25f * (x0u.y + sdu * (a1.y + a2.y + a3.y));
    float gi0 = 0.25f * (x0i.x + sdi * (b1.x + b2.x + b3.x));
    float gi1 = 0.25f * (x0i.y + sdi * (b1.y + b2.y + b3.y));

    float2 pv = ((const float2*)g_proj)[(size_t)w * 32 + lane];
    float2 tv = ((const float2*)Tu)[ou];

    float d1 = gu0 * gi0 + gu1 * gi1;
    float ss = pv.x * pv.x + pv.y * pv.y;
    float d2 = tv.x * pv.x + tv.y * pv.y;

    #pragma unroll
    for (int o = 16; o > 0; o >>= 1) {
        d1 += __shfl_xor_sync(0xffffffffu, d1, o);
        ss += __shfl_xor_sync(0xffffffffu, ss, o);
        d2 += __shfl_xor_sync(0xffffffffu, d2, o);
    }
    if (lane == 0) {
        float inv = 1.0f / fmaxf(sqrtf(ss), 1e-12f);
        out[w] = d1 + d2 * inv;
    }
}

// ---------------- launch ----------------
extern "C" void kernel_launch(void* const* d_in, const int* in_sizes, int n_in,
                              void* d_out, int out_size) {
    const float* Gu    = (const float*)d_in[0];
    const float* Gi    = (const float*)d_in[1];
    const float* Tu    = (const float*)d_in[2];
    const float* F     = (const float*)d_in[3];
    const float* W     = (const float*)d_in[4];
    const float* bias  = (const float*)d_in[5];
    const int*   ue    = (const int*)d_in[6];
    const int*   ie    = (const int*)d_in[7];
    const int*   users = (const int*)d_in[8];
    const int*   items = (const int*)d_in[9];
    float*       out   = (float*)d_out;

    (void)in_sizes; (void)n_in; (void)out_size;

    k_zero<<<(NN + 255) / 256, 256>>>();
    k_mark<<<(NB + 255) / 256, 256>>>(users, items);
    k_deg<<<(NE + 255) / 256, 256>>>(ue, ie);
    k_part<<<NPART, 256>>>();
    k_scanpart<<<1, 1024>>>();
    k_off<<<NPART, 256>>>();
    k_scatter<<<(NE + 255) / 256, 256>>>(ue, ie);
    k_init<<<(NN * EMB / 4 + 255) / 256, 256>>>(Gu, Gi);

    k_prop<<<(NN * 32 + 255) / 256, 256>>>(0, 0);   // wa -> wb  (w1, all nodes)
    k_prop<<<(NN * 32 + 255) / 256, 256>>>(1, 0);   // wb -> wc  (w2, all nodes)
    k_prop<<<(NN * 32 + 255) / 256, 256>>>(2, 1);   // wc -> wa  (w3, batch nodes only)

    k_gemm<<<NB / 64, 256>>>(F, W, bias, items);
    k_score<<<(NB * 32 + 255) / 256, 256>>>(Gu, Gi, Tu, users, items, out);
}

// round 13
// speedup vs baseline: 2.6189x; 1.1038x over previous
#include <cuda_runtime.h>
#include <cuda_fp16.h>
#include <cstdint>

#define NU   100000
#define NI   50000
#define NN   (NU + NI)          // 150000
#define EMB  64
#define NE   3000000            // edges per direction (total dir. edges = 2*NE)
#define FDIM 1024
#define NB   16384
#define NPART ((NN + 255) / 256)   // 586

// ---------------- static device scratch ----------------
__device__ __half g_wa[(size_t)NN * EMB];   // w0, later w3
__device__ __half g_wb[(size_t)NN * EMB];   // w1
__device__ __half g_wc[(size_t)NN * EMB];   // w2
__device__ int   g_deg[NN];
__device__ int   g_off[NN];
__device__ int   g_cur[NN];
__device__ float g_dinv[NN];
__device__ unsigned char g_flag[NN];
__device__ int   g_part[1024];
__device__ int   g_csr[(size_t)2 * NE];    // src index only
__device__ float g_proj[(size_t)NB * EMB];

// ---------------- graph build ----------------
__global__ void k_zero() {
    int n = blockIdx.x * blockDim.x + threadIdx.x;
    if (n < NN) { g_deg[n] = 0; g_flag[n] = 0; }
}

__global__ void k_mark(const int* __restrict__ users, const int* __restrict__ items) {
    int i = blockIdx.x * blockDim.x + threadIdx.x;
    if (i < NB) {
        g_flag[users[i]] = 1;
        g_flag[NU + items[i]] = 1;
    }
}

__global__ void k_deg(const int* __restrict__ ue, const int* __restrict__ ie) {
    int e = blockIdx.x * blockDim.x + threadIdx.x;
    if (e < NE) {
        atomicAdd(&g_deg[ue[e]], 1);
        atomicAdd(&g_deg[ie[e] + NU], 1);
    }
}

// phase A: per-block sum of degrees (also computes dinv)
__global__ void __launch_bounds__(256) k_part() {
    __shared__ int s[256];
    int t = threadIdx.x;
    int n = blockIdx.x * 256 + t;
    int d = (n < NN) ? g_deg[n] : 0;
    if (n < NN) g_dinv[n] = (d > 0) ? rsqrtf((float)d) : 0.0f;
    s[t] = d;
    __syncthreads();
    #pragma unroll
    for (int o = 128; o > 0; o >>= 1) {
        if (t < o) s[t] += s[t + o];
        __syncthreads();
    }
    if (t == 0) g_part[blockIdx.x] = s[0];
}

// phase B: single-block exclusive scan of the partials
__global__ void __launch_bounds__(1024) k_scanpart() {
    __shared__ int s[1024];
    int t = threadIdx.x;
    int v = (t < NPART) ? g_part[t] : 0;
    s[t] = v;
    __syncthreads();
    #pragma unroll
    for (int o = 1; o < 1024; o <<= 1) {
        int u = (t >= o) ? s[t - o] : 0;
        __syncthreads();
        s[t] += u;
        __syncthreads();
    }
    if (t < NPART) g_part[t] = s[t] - v;   // exclusive
}

// phase C: per-block local scan + partial base -> offsets
__global__ void __launch_bounds__(256) k_off() {
    __shared__ int s[256];
    int t = threadIdx.x;
    int n = blockIdx.x * 256 + t;
    int d = (n < NN) ? g_deg[n] : 0;
    s[t] = d;
    __syncthreads();
    #pragma unroll
    for (int o = 1; o < 256; o <<= 1) {
        int u = (t >= o) ? s[t - o] : 0;
        __syncthreads();
        s[t] += u;
        __syncthreads();
    }
    if (n < NN) {
        int off = g_part[blockIdx.x] + s[t] - d;
        g_off[n] = off;
        g_cur[n] = off;
    }
}

__global__ void k_scatter(const int* __restrict__ ue, const int* __restrict__ ie) {
    int e = blockIdx.x * blockDim.x + threadIdx.x;
    if (e < NE) {
        int u  = ue[e];
        int it = ie[e] + NU;
        int p1 = atomicAdd(&g_cur[it], 1);
        g_csr[p1] = u;
        int p2 = atomicAdd(&g_cur[u], 1);
        g_csr[p2] = it;
    }
}

// w0 = fp16(dinv * x0)
__global__ void k_init(const float* __restrict__ Gu, const float* __restrict__ Gi) {
    int i = blockIdx.x * blockDim.x + threadIdx.x;
    if (i < NN * EMB / 4) {
        int node = i >> 4;   // EMB/4 = 16 float4 per node
        const float4* src = (node < NU) ? (const float4*)Gu
                                        : (const float4*)Gi - (size_t)NU * 16;
        float4 v = src[i];
        float d = g_dinv[node];
        __half2 h0 = __floats2half2_rn(v.x * d, v.y * d);
        __half2 h1 = __floats2half2_rn(v.z * d, v.w * d);
        ((__half2*)g_wa)[2 * i]     = h0;
        ((__half2*)g_wa)[2 * i + 1] = h1;
    }
}

// ---------------- propagation: 4 dst nodes per warp, 8 lanes/node, LDG.128 gathers ----------------
// Each fp16 row is 128B = 8 x uint4. Lane sub (0..7) owns 16B of the row.
// One LDG.128 instruction services 4 edges (one per group).
__device__ __forceinline__ void acc8(uint4 q, float* s) {
    float2 v0 = __half22float2(*(__half2*)&q.x);
    float2 v1 = __half22float2(*(__half2*)&q.y);
    float2 v2 = __half22float2(*(__half2*)&q.z);
    float2 v3 = __half22float2(*(__half2*)&q.w);
    s[0] += v0.x; s[1] += v0.y; s[2] += v1.x; s[3] += v1.y;
    s[4] += v2.x; s[5] += v2.y; s[6] += v3.x; s[7] += v3.y;
}

__global__ void __launch_bounds__(256) k_prop(int sel, int pruned) {
    const uint4* __restrict__ xin;
    uint4* __restrict__ xout;
    if (sel == 0)      { xin = (const uint4*)g_wa; xout = (uint4*)g_wb; }
    else if (sel == 1) { xin = (const uint4*)g_wb; xout = (uint4*)g_wc; }
    else               { xin = (const uint4*)g_wc; xout = (uint4*)g_wa; }

    int warpId = (blockIdx.x * blockDim.x + threadIdx.x) >> 5;
    int lane   = threadIdx.x & 31;
    int grp    = lane >> 3;    // 0..3: node within warp
    int sub    = lane & 7;     // 0..7: 16B chunk within row

    int node = warpId * 4 + grp;
    if (node >= NN) return;
    if (pruned && !g_flag[node]) return;

    int cnt = g_deg[node];
    const int* __restrict__ csr = g_csr + g_off[node];

    float s[8] = {0, 0, 0, 0, 0, 0, 0, 0};
    int i = 0;
    // head until csr pointer is 16B aligned
    while (i < cnt && (((size_t)(csr + i)) & 15)) {
        int r = csr[i++];
        acc8(xin[(size_t)r * 8 + sub], s);
    }
    // main: 1 broadcast int4 (serves 4 iters) + 4 LDG.128 gathers in flight
    for (; i + 8 <= cnt; i += 8) {
        int4 ra = *(const int4*)(csr + i);
        int4 rb = *(const int4*)(csr + i + 4);
        uint4 q0 = xin[(size_t)ra.x * 8 + sub];
        uint4 q1 = xin[(size_t)ra.y * 8 + sub];
        uint4 q2 = xin[(size_t)ra.z * 8 + sub];
        uint4 q3 = xin[(size_t)ra.w * 8 + sub];
        uint4 q4 = xin[(size_t)rb.x * 8 + sub];
        uint4 q5 = xin[(size_t)rb.y * 8 + sub];
        uint4 q6 = xin[(size_t)rb.z * 8 + sub];
        uint4 q7 = xin[(size_t)rb.w * 8 + sub];
        acc8(q0, s); acc8(q1, s); acc8(q2, s); acc8(q3, s);
        acc8(q4, s); acc8(q5, s); acc8(q6, s); acc8(q7, s);
    }
    for (; i + 4 <= cnt; i += 4) {
        int4 r = *(const int4*)(csr + i);
        uint4 q0 = xin[(size_t)r.x * 8 + sub];
        uint4 q1 = xin[(size_t)r.y * 8 + sub];
        uint4 q2 = xin[(size_t)r.z * 8 + sub];
        uint4 q3 = xin[(size_t)r.w * 8 + sub];
        acc8(q0, s); acc8(q1, s); acc8(q2, s); acc8(q3, s);
    }
    for (; i < cnt; i++) {
        int r = csr[i];
        acc8(xin[(size_t)r * 8 + sub], s);
    }

    float d  = g_dinv[node];
    float d2 = d * d;
    __half2 h0 = __floats2half2_rn(s[0] * d2, s[1] * d2);
    __half2 h1 = __floats2half2_rn(s[2] * d2, s[3] * d2);
    __half2 h2 = __floats2half2_rn(s[4] * d2, s[5] * d2);
    __half2 h3 = __floats2half2_rn(s[6] * d2, s[7] * d2);
    uint4 o;
    o.x = *(uint32_t*)&h0; o.y = *(uint32_t*)&h1;
    o.z = *(uint32_t*)&h2; o.w = *(uint32_t*)&h3;
    xout[(size_t)node * 8 + sub] = o;
}

// ---------------- projection GEMM via tensor cores (fp16 hi/lo split, fp32 accum) ----------------
#define MMA16816(C, A, B)                                                        \
    asm volatile("mma.sync.aligned.m16n8k16.row.col.f32.f16.f16.f32 "            \
                 "{%0,%1,%2,%3}, {%4,%5,%6,%7}, {%8,%9}, {%0,%1,%2,%3};"         \
                 : "+f"((C)[0]), "+f"((C)[1]), "+f"((C)[2]), "+f"((C)[3])        \
                 : "r"((A)[0]), "r"((A)[1]), "r"((A)[2]), "r"((A)[3]),           \
                   "r"((B)[0]), "r"((B)[1]))

__global__ void __launch_bounds__(256) k_gemm(const float* __restrict__ F,
                                              const float* __restrict__ W,
                                              const float* __restrict__ bias,
                                              const int* __restrict__ items) {
    __shared__ __half sFhi[64][40];
    __shared__ __half sFlo[64][40];
    __shared__ __half sWhi[64][40];
    __shared__ __half sWlo[64][40];
    __shared__ int si[64];

    int t    = threadIdx.x;
    int base = blockIdx.x * 64;
    if (t < 64) si[t] = items[base + t];
    __syncthreads();

    int warp = t >> 5, lane = t & 31;
    int g = lane >> 2, tc = lane & 3;
    int mr    = (warp & 3) * 16;
    int nbase = (warp >> 2) * 32;

    float acc[4][4];
    #pragma unroll
    for (int a = 0; a < 4; a++)
        #pragma unroll
        for (int b = 0; b < 4; b++) acc[a][b] = 0.0f;

    for (int k0 = 0; k0 < FDIM; k0 += 32) {
        #pragma unroll
        for (int j = 0; j < 2; j++) {
            int idx = j * 256 + t;     // 0..511
            int row = idx >> 3;
            int c   = (idx & 7) * 4;
            float4 v = *(const float4*)(F + (size_t)si[row] * FDIM + k0 + c);
            __half h;
            h = __float2half_rn(v.x); sFhi[row][c+0] = h; sFlo[row][c+0] = __float2half_rn(v.x - __half2float(h));
            h = __float2half_rn(v.y); sFhi[row][c+1] = h; sFlo[row][c+1] = __float2half_rn(v.y - __half2float(h));
            h = __float2half_rn(v.z); sFhi[row][c+2] = h; sFlo[row][c+2] = __float2half_rn(v.z - __half2float(h));
            h = __float2half_rn(v.w); sFhi[row][c+3] = h; sFlo[row][c+3] = __float2half_rn(v.w - __half2float(h));
            float4 wv = *(const float4*)(W + (size_t)row * FDIM + k0 + c);
            h = __float2half_rn(wv.x); sWhi[row][c+0] = h; sWlo[row][c+0] = __float2half_rn(wv.x - __half2float(h));
            h = __float2half_rn(wv.y); sWhi[row][c+1] = h; sWlo[row][c+1] = __float2half_rn(wv.y - __half2float(h));
            h = __float2half_rn(wv.z); sWhi[row][c+2] = h; sWlo[row][c+2] = __float2half_rn(wv.z - __half2float(h));
            h = __float2half_rn(wv.w); sWhi[row][c+3] = h; sWlo[row][c+3] = __float2half_rn(wv.w - __half2float(h));
        }
        __syncthreads();

        #pragma unroll
        for (int ks = 0; ks < 2; ks++) {
            int kb = ks * 16;
            uint32_t ah[4], al[4];
            ah[0] = *(const uint32_t*)&sFhi[mr + g    ][kb + 2 * tc];
            ah[1] = *(const uint32_t*)&sFhi[mr + g + 8][kb + 2 * tc];
            ah[2] = *(const uint32_t*)&sFhi[mr + g    ][kb + 8 + 2 * tc];
            ah[3] = *(const uint32_t*)&sFhi[mr + g + 8][kb + 8 + 2 * tc];
            al[0] = *(const uint32_t*)&sFlo[mr + g    ][kb + 2 * tc];
            al[1] = *(const uint32_t*)&sFlo[mr + g + 8][kb + 2 * tc];
            al[2] = *(const uint32_t*)&sFlo[mr + g    ][kb + 8 + 2 * tc];
            al[3] = *(const uint32_t*)&sFlo[mr + g + 8][kb + 8 + 2 * tc];
            #pragma unroll
            for (int nt = 0; nt < 4; nt++) {
                int n0 = nbase + nt * 8;
                uint32_t bh[2], bl[2];
                bh[0] = *(const uint32_t*)&sWhi[n0 + g][kb + 2 * tc];
                bh[1] = *(const uint32_t*)&sWhi[n0 + g][kb + 8 + 2 * tc];
                bl[0] = *(const uint32_t*)&sWlo[n0 + g][kb + 2 * tc];
                bl[1] = *(const uint32_t*)&sWlo[n0 + g][kb + 8 + 2 * tc];
                MMA16816(acc[nt], ah, bh);
                MMA16816(acc[nt], ah, bl);
                MMA16816(acc[nt], al, bh);
            }
        }
        __syncthreads();
    }

    #pragma unroll
    for (int nt = 0; nt < 4; nt++) {
        int c0 = nbase + nt * 8 + 2 * tc;
        int r0 = base + mr + g;
        g_proj[(size_t)r0 * EMB + c0]           = acc[nt][0] + bias[c0];
        g_proj[(size_t)r0 * EMB + c0 + 1]       = acc[nt][1] + bias[c0 + 1];
        g_proj[(size_t)(r0 + 8) * EMB + c0]     = acc[nt][2] + bias[c0];
        g_proj[(size_t)(r0 + 8) * EMB + c0 + 1] = acc[nt][3] + bias[c0 + 1];
    }
}

// ---------------- final scoring: one warp per batch element ----------------
__global__ void __launch_bounds__(256) k_score(const float* __restrict__ Gu,
                                               const float* __restrict__ Gi,
                                               const float* __restrict__ Tu,
                                               const int* __restrict__ users,
                                               const int* __restrict__ items,
                                               float* __restrict__ out) {
    int w    = (blockIdx.x * blockDim.x + threadIdx.x) >> 5;
    int lane = threadIdx.x & 31;
    if (w >= NB) return;

    int u  = users[w];
    int it = items[w];
    int ni = NU + it;

    const __half2* w1 = (const __half2*)g_wb;
    const __half2* w2 = (const __half2*)g_wc;
    const __half2* w3 = (const __half2*)g_wa;

    size_t ou = (size_t)u * 32 + lane;
    size_t oi = (size_t)ni * 32 + lane;

    float sdu = sqrtf((float)g_deg[u]);
    float sdi = sqrtf((float)g_deg[ni]);

    float2 x0u = ((const float2*)Gu)[ou];
    float2 x0i = ((const float2*)Gi)[(size_t)it * 32 + lane];
    float2 a1 = __half22float2(w1[ou]);
    float2 a2 = __half22float2(w2[ou]);
    float2 a3 = __half22float2(w3[ou]);
    float2 b1 = __half22float2(w1[oi]);
    float2 b2 = __half22float2(w2[oi]);
    float2 b3 = __half22float2(w3[oi]);

    float gu0 = 0.25f * (x0u.x + sdu * (a1.x + a2.x + a3.x));
    float gu1 = 0.25f * (x0u.y + sdu * (a1.y + a2.y + a3.y));
    float gi0 = 0.25f * (x0i.x + sdi * (b1.x + b2.x + b3.x));
    float gi1 = 0.25f * (x0i.y + sdi * (b1.y + b2.y + b3.y));

    float2 pv = ((const float2*)g_proj)[(size_t)w * 32 + lane];
    float2 tv = ((const float2*)Tu)[ou];

    float d1 = gu0 * gi0 + gu1 * gi1;
    float ss = pv.x * pv.x + pv.y * pv.y;
    float d2 = tv.x * pv.x + tv.y * pv.y;

    #pragma unroll
    for (int o = 16; o > 0; o >>= 1) {
        d1 += __shfl_xor_sync(0xffffffffu, d1, o);
        ss += __shfl_xor_sync(0xffffffffu, ss, o);
        d2 += __shfl_xor_sync(0xffffffffu, d2, o);
    }
    if (lane == 0) {
        float inv = 1.0f / fmaxf(sqrtf(ss), 1e-12f);
        out[w] = d1 + d2 * inv;
    }
}

// ---------------- launch ----------------
extern "C" void kernel_launch(void* const* d_in, const int* in_sizes, int n_in,
                              void* d_out, int out_size) {
    const float* Gu    = (const float*)d_in[0];
    const float* Gi    = (const float*)d_in[1];
    const float* Tu    = (const float*)d_in[2];
    const float* F     = (const float*)d_in[3];
    const float* W     = (const float*)d_in[4];
    const float* bias  = (const float*)d_in[5];
    const int*   ue    = (const int*)d_in[6];
    const int*   ie    = (const int*)d_in[7];
    const int*   users = (const int*)d_in[8];
    const int*   items = (const int*)d_in[9];
    float*       out   = (float*)d_out;

    (void)in_sizes; (void)n_in; (void)out_size;

    k_zero<<<(NN + 255) / 256, 256>>>();
    k_mark<<<(NB + 255) / 256, 256>>>(users, items);
    k_deg<<<(NE + 255) / 256, 256>>>(ue, ie);
    k_part<<<NPART, 256>>>();
    k_scanpart<<<1, 1024>>>();
    k_off<<<NPART, 256>>>();
    k_scatter<<<(NE + 255) / 256, 256>>>(ue, ie);
    k_init<<<(NN * EMB / 4 + 255) / 256, 256>>>(Gu, Gi);

    // 4 nodes per warp => NN/4 warps
    int prop_threads = ((NN + 3) / 4) * 32;
    int prop_blocks  = (prop_threads + 255) / 256;
    k_prop<<<prop_blocks, 256>>>(0, 0);   // wa -> wb  (w1, all nodes)
    k_prop<<<prop_blocks, 256>>>(1, 0);   // wb -> wc  (w2, all nodes)
    k_prop<<<prop_blocks, 256>>>(2, 1);   // wc -> wa  (w3, batch nodes only)

    k_gemm<<<NB / 64, 256>>>(F, W, bias, items);
    k_score<<<(NB * 32 + 255) / 256, 256>>>(Gu, Gi, Tu, users, items, out);
}

// round 14
// speedup vs baseline: 2.6266x; 1.0029x over previous
#include <cuda_runtime.h>
#include <cuda_fp16.h>
#include <cstdint>

#define NU   100000
#define NI   50000
#define NN   (NU + NI)          // 150000
#define EMB  64
#define NE   3000000            // edges per direction (total dir. edges = 2*NE)
#define FDIM 1024
#define NB   16384
#define NPART ((NN + 255) / 256)   // 586

// ---------------- static device scratch ----------------
__device__ __half g_wa[(size_t)NN * EMB];   // w0, later w3
__device__ __half g_wb[(size_t)NN * EMB];   // w1
__device__ __half g_wc[(size_t)NN * EMB];   // w2
__device__ int   g_deg[NN];
__device__ int   g_off[NN];
__device__ float g_dinv[NN];
__device__ unsigned char g_flag[NN];
__device__ int   g_part[1024];
__device__ int   g_rank_u[NE];             // rank of edge e within user u's list
__device__ int   g_rank_i[NE];             // rank of edge e within item it's list
__device__ int   g_csr[(size_t)2 * NE];    // src index only
__device__ float g_proj[(size_t)NB * EMB];

// ---------------- graph build ----------------
__global__ void k_zero() {
    int n = blockIdx.x * blockDim.x + threadIdx.x;
    if (n < NN) { g_deg[n] = 0; g_flag[n] = 0; }
}

__global__ void k_mark(const int* __restrict__ users, const int* __restrict__ items) {
    int i = blockIdx.x * blockDim.x + threadIdx.x;
    if (i < NB) {
        g_flag[users[i]] = 1;
        g_flag[NU + items[i]] = 1;
    }
}

// degree count; also captures each edge's rank within its dst segment (reused by scatter)
__global__ void k_deg(const int* __restrict__ ue, const int* __restrict__ ie) {
    int e4 = blockIdx.x * blockDim.x + threadIdx.x;
    if (e4 * 4 + 4 <= NE) {
        int e = e4 * 4;
        int4 u = *(const int4*)(ue + e);
        int4 v = *(const int4*)(ie + e);
        int4 ru, ri;
        ru.x = atomicAdd(&g_deg[u.x], 1);
        ru.y = atomicAdd(&g_deg[u.y], 1);
        ru.z = atomicAdd(&g_deg[u.z], 1);
        ru.w = atomicAdd(&g_deg[u.w], 1);
        ri.x = atomicAdd(&g_deg[v.x + NU], 1);
        ri.y = atomicAdd(&g_deg[v.y + NU], 1);
        ri.z = atomicAdd(&g_deg[v.z + NU], 1);
        ri.w = atomicAdd(&g_deg[v.w + NU], 1);
        *(int4*)(g_rank_u + e) = ru;
        *(int4*)(g_rank_i + e) = ri;
    } else {
        for (int e = e4 * 4; e < NE; e++) {
            g_rank_u[e] = atomicAdd(&g_deg[ue[e]], 1);
            g_rank_i[e] = atomicAdd(&g_deg[ie[e] + NU], 1);
        }
    }
}

// phase A: per-block sum of degrees (also computes dinv)
__global__ void __launch_bounds__(256) k_part() {
    __shared__ int s[256];
    int t = threadIdx.x;
    int n = blockIdx.x * 256 + t;
    int d = (n < NN) ? g_deg[n] : 0;
    if (n < NN) g_dinv[n] = (d > 0) ? rsqrtf((float)d) : 0.0f;
    s[t] = d;
    __syncthreads();
    #pragma unroll
    for (int o = 128; o > 0; o >>= 1) {
        if (t < o) s[t] += s[t + o];
        __syncthreads();
    }
    if (t == 0) g_part[blockIdx.x] = s[0];
}

// phase B: single-block exclusive scan of the partials
__global__ void __launch_bounds__(1024) k_scanpart() {
    __shared__ int s[1024];
    int t = threadIdx.x;
    int v = (t < NPART) ? g_part[t] : 0;
    s[t] = v;
    __syncthreads();
    #pragma unroll
    for (int o = 1; o < 1024; o <<= 1) {
        int u = (t >= o) ? s[t - o] : 0;
        __syncthreads();
        s[t] += u;
        __syncthreads();
    }
    if (t < NPART) g_part[t] = s[t] - v;   // exclusive
}

// phase C: per-block local scan + partial base -> offsets
__global__ void __launch_bounds__(256) k_off() {
    __shared__ int s[256];
    int t = threadIdx.x;
    int n = blockIdx.x * 256 + t;
    int d = (n < NN) ? g_deg[n] : 0;
    s[t] = d;
    __syncthreads();
    #pragma unroll
    for (int o = 1; o < 256; o <<= 1) {
        int u = (t >= o) ? s[t - o] : 0;
        __syncthreads();
        s[t] += u;
        __syncthreads();
    }
    if (n < NN) g_off[n] = g_part[blockIdx.x] + s[t] - d;
}

// scatter with precomputed ranks: NO atomics, only the irreducible random stores
__global__ void k_scatter(const int* __restrict__ ue, const int* __restrict__ ie) {
    int e4 = blockIdx.x * blockDim.x + threadIdx.x;
    if (e4 * 4 + 4 <= NE) {
        int e = e4 * 4;
        int4 u  = *(const int4*)(ue + e);
        int4 v  = *(const int4*)(ie + e);
        int4 ru = *(const int4*)(g_rank_u + e);
        int4 ri = *(const int4*)(g_rank_i + e);
        g_csr[g_off[v.x + NU] + ri.x] = u.x;
        g_csr[g_off[v.y + NU] + ri.y] = u.y;
        g_csr[g_off[v.z + NU] + ri.z] = u.z;
        g_csr[g_off[v.w + NU] + ri.w] = u.w;
        g_csr[g_off[u.x] + ru.x] = v.x + NU;
        g_csr[g_off[u.y] + ru.y] = v.y + NU;
        g_csr[g_off[u.z] + ru.z] = v.z + NU;
        g_csr[g_off[u.w] + ru.w] = v.w + NU;
    } else {
        for (int e = e4 * 4; e < NE; e++) {
            int u  = ue[e];
            int it = ie[e] + NU;
            g_csr[g_off[it] + g_rank_i[e]] = u;
            g_csr[g_off[u]  + g_rank_u[e]] = it;
        }
    }
}

// w0 = fp16(dinv * x0)
__global__ void k_init(const float* __restrict__ Gu, const float* __restrict__ Gi) {
    int i = blockIdx.x * blockDim.x + threadIdx.x;
    if (i < NN * EMB / 4) {
        int node = i >> 4;   // EMB/4 = 16 float4 per node
        const float4* src = (node < NU) ? (const float4*)Gu
                                        : (const float4*)Gi - (size_t)NU * 16;
        float4 v = src[i];
        float d = g_dinv[node];
        __half2 h0 = __floats2half2_rn(v.x * d, v.y * d);
        __half2 h1 = __floats2half2_rn(v.z * d, v.w * d);
        ((__half2*)g_wa)[2 * i]     = h0;
        ((__half2*)g_wa)[2 * i + 1] = h1;
    }
}

// ---------------- propagation: 4 dst nodes per warp, 8 lanes/node, LDG.128 gathers ----------------
__device__ __forceinline__ void acc8(uint4 q, float* s) {
    float2 v0 = __half22float2(*(__half2*)&q.x);
    float2 v1 = __half22float2(*(__half2*)&q.y);
    float2 v2 = __half22float2(*(__half2*)&q.z);
    float2 v3 = __half22float2(*(__half2*)&q.w);
    s[0] += v0.x; s[1] += v0.y; s[2] += v1.x; s[3] += v1.y;
    s[4] += v2.x; s[5] += v2.y; s[6] += v3.x; s[7] += v3.y;
}

__global__ void __launch_bounds__(256) k_prop(int sel, int pruned) {
    const uint4* __restrict__ xin;
    uint4* __restrict__ xout;
    if (sel == 0)      { xin = (const uint4*)g_wa; xout = (uint4*)g_wb; }
    else if (sel == 1) { xin = (const uint4*)g_wb; xout = (uint4*)g_wc; }
    else               { xin = (const uint4*)g_wc; xout = (uint4*)g_wa; }

    int warpId = (blockIdx.x * blockDim.x + threadIdx.x) >> 5;
    int lane   = threadIdx.x & 31;
    int grp    = lane >> 3;    // 0..3: node within warp
    int sub    = lane & 7;     // 0..7: 16B chunk within row

    int node = warpId * 4 + grp;
    if (node >= NN) return;
    if (pruned && !g_flag[node]) return;

    int cnt = g_deg[node];
    const int* __restrict__ csr = g_csr + g_off[node];

    float s[8] = {0, 0, 0, 0, 0, 0, 0, 0};
    int i = 0;
    while (i < cnt && (((size_t)(csr + i)) & 15)) {
        int r = csr[i++];
        acc8(xin[(size_t)r * 8 + sub], s);
    }
    for (; i + 8 <= cnt; i += 8) {
        int4 ra = *(const int4*)(csr + i);
        int4 rb = *(const int4*)(csr + i + 4);
        uint4 q0 = xin[(size_t)ra.x * 8 + sub];
        uint4 q1 = xin[(size_t)ra.y * 8 + sub];
        uint4 q2 = xin[(size_t)ra.z * 8 + sub];
        uint4 q3 = xin[(size_t)ra.w * 8 + sub];
        uint4 q4 = xin[(size_t)rb.x * 8 + sub];
        uint4 q5 = xin[(size_t)rb.y * 8 + sub];
        uint4 q6 = xin[(size_t)rb.z * 8 + sub];
        uint4 q7 = xin[(size_t)rb.w * 8 + sub];
        acc8(q0, s); acc8(q1, s); acc8(q2, s); acc8(q3, s);
        acc8(q4, s); acc8(q5, s); acc8(q6, s); acc8(q7, s);
    }
    for (; i + 4 <= cnt; i += 4) {
        int4 r = *(const int4*)(csr + i);
        uint4 q0 = xin[(size_t)r.x * 8 + sub];
        uint4 q1 = xin[(size_t)r.y * 8 + sub];
        uint4 q2 = xin[(size_t)r.z * 8 + sub];
        uint4 q3 = xin[(size_t)r.w * 8 + sub];
        acc8(q0, s); acc8(q1, s); acc8(q2, s); acc8(q3, s);
    }
    for (; i < cnt; i++) {
        int r = csr[i];
        acc8(xin[(size_t)r * 8 + sub], s);
    }

    float d  = g_dinv[node];
    float d2 = d * d;
    __half2 h0 = __floats2half2_rn(s[0] * d2, s[1] * d2);
    __half2 h1 = __floats2half2_rn(s[2] * d2, s[3] * d2);
    __half2 h2 = __floats2half2_rn(s[4] * d2, s[5] * d2);
    __half2 h3 = __floats2half2_rn(s[6] * d2, s[7] * d2);
    uint4 o;
    o.x = *(uint32_t*)&h0; o.y = *(uint32_t*)&h1;
    o.z = *(uint32_t*)&h2; o.w = *(uint32_t*)&h3;
    xout[(size_t)node * 8 + sub] = o;
}

// ---------------- projection GEMM via tensor cores (fp16 hi/lo split, fp32 accum) ----------------
#define MMA16816(C, A, B)                                                        \
    asm volatile("mma.sync.aligned.m16n8k16.row.col.f32.f16.f16.f32 "            \
                 "{%0,%1,%2,%3}, {%4,%5,%6,%7}, {%8,%9}, {%0,%1,%2,%3};"         \
                 : "+f"((C)[0]), "+f"((C)[1]), "+f"((C)[2]), "+f"((C)[3])        \
                 : "r"((A)[0]), "r"((A)[1]), "r"((A)[2]), "r"((A)[3]),           \
                   "r"((B)[0]), "r"((B)[1]))

__global__ void __launch_bounds__(256) k_gemm(const float* __restrict__ F,
                                              const float* __restrict__ W,
                                              const float* __restrict__ bias,
                                              const int* __restrict__ items) {
    __shared__ __half sFhi[64][40];
    __shared__ __half sFlo[64][40];
    __shared__ __half sWhi[64][40];
    __shared__ __half sWlo[64][40];
    __shared__ int si[64];

    int t    = threadIdx.x;
    int base = blockIdx.x * 64;
    if (t < 64) si[t] = items[base + t];
    __syncthreads();

    int warp = t >> 5, lane = t & 31;
    int g = lane >> 2, tc = lane & 3;
    int mr    = (warp & 3) * 16;
    int nbase = (warp >> 2) * 32;

    float acc[4][4];
    #pragma unroll
    for (int a = 0; a < 4; a++)
        #pragma unroll
        for (int b = 0; b < 4; b++) acc[a][b] = 0.0f;

    for (int k0 = 0; k0 < FDIM; k0 += 32) {
        #pragma unroll
        for (int j = 0; j < 2; j++) {
            int idx = j * 256 + t;     // 0..511
            int row = idx >> 3;
            int c   = (idx & 7) * 4;
            float4 v = *(const float4*)(F + (size_t)si[row] * FDIM + k0 + c);
            __half h;
            h = __float2half_rn(v.x); sFhi[row][c+0] = h; sFlo[row][c+0] = __float2half_rn(v.x - __half2float(h));
            h = __float2half_rn(v.y); sFhi[row][c+1] = h; sFlo[row][c+1] = __float2half_rn(v.y - __half2float(h));
            h = __float2half_rn(v.z); sFhi[row][c+2] = h; sFlo[row][c+2] = __float2half_rn(v.z - __half2float(h));
            h = __float2half_rn(v.w); sFhi[row][c+3] = h; sFlo[row][c+3] = __float2half_rn(v.w - __half2float(h));
            float4 wv = *(const float4*)(W + (size_t)row * FDIM + k0 + c);
            h = __float2half_rn(wv.x); sWhi[row][c+0] = h; sWlo[row][c+0] = __float2half_rn(wv.x - __half2float(h));
            h = __float2half_rn(wv.y); sWhi[row][c+1] = h; sWlo[row][c+1] = __float2half_rn(wv.y - __half2float(h));
            h = __float2half_rn(wv.z); sWhi[row][c+2] = h; sWlo[row][c+2] = __float2half_rn(wv.z - __half2float(h));
            h = __float2half_rn(wv.w); sWhi[row][c+3] = h; sWlo[row][c+3] = __float2half_rn(wv.w - __half2float(h));
        }
        __syncthreads();

        #pragma unroll
        for (int ks = 0; ks < 2; ks++) {
            int kb = ks * 16;
            uint32_t ah[4], al[4];
            ah[0] = *(const uint32_t*)&sFhi[mr + g    ][kb + 2 * tc];
            ah[1] = *(const uint32_t*)&sFhi[mr + g + 8][kb + 2 * tc];
            ah[2] = *(const uint32_t*)&sFhi[mr + g    ][kb + 8 + 2 * tc];
            ah[3] = *(const uint32_t*)&sFhi[mr + g + 8][kb + 8 + 2 * tc];
            al[0] = *(const uint32_t*)&sFlo[mr + g    ][kb + 2 * tc];
            al[1] = *(const uint32_t*)&sFlo[mr + g + 8][kb + 2 * tc];
            al[2] = *(const uint32_t*)&sFlo[mr + g    ][kb + 8 + 2 * tc];
            al[3] = *(const uint32_t*)&sFlo[mr + g + 8][kb + 8 + 2 * tc];
            #pragma unroll
            for (int nt = 0; nt < 4; nt++) {
                int n0 = nbase + nt * 8;
                uint32_t bh[2], bl[2];
                bh[0] = *(const uint32_t*)&sWhi[n0 + g][kb + 2 * tc];
                bh[1] = *(const uint32_t*)&sWhi[n0 + g][kb + 8 + 2 * tc];
                bl[0] = *(const uint32_t*)&sWlo[n0 + g][kb + 2 * tc];
                bl[1] = *(const uint32_t*)&sWlo[n0 + g][kb + 8 + 2 * tc];
                MMA16816(acc[nt], ah, bh);
                MMA16816(acc[nt], ah, bl);
                MMA16816(acc[nt], al, bh);
            }
        }
        __syncthreads();
    }

    #pragma unroll
    for (int nt = 0; nt < 4; nt++) {
        int c0 = nbase + nt * 8 + 2 * tc;
        int r0 = base + mr + g;
        g_proj[(size_t)r0 * EMB + c0]           = acc[nt][0] + bias[c0];
        g_proj[(size_t)r0 * EMB + c0 + 1]       = acc[nt][1] + bias[c0 + 1];
        g_proj[(size_t)(r0 + 8) * EMB + c0]     = acc[nt][2] + bias[c0];
        g_proj[(size_t)(r0 + 8) * EMB + c0 + 1] = acc[nt][3] + bias[c0 + 1];
    }
}

// ---------------- final scoring: one warp per batch element ----------------
__global__ void __launch_bounds__(256) k_score(const float* __restrict__ Gu,
                                               const float* __restrict__ Gi,
                                               const float* __restrict__ Tu,
                                               const int* __restrict__ users,
                                               const int* __restrict__ items,
                                               float* __restrict__ out) {
    int w    = (blockIdx.x * blockDim.x + threadIdx.x) >> 5;
    int lane = threadIdx.x & 31;
    if (w >= NB) return;

    int u  = users[w];
    int it = items[w];
    int ni = NU + it;

    const __half2* w1 = (const __half2*)g_wb;
    const __half2* w2 = (const __half2*)g_wc;
    const __half2* w3 = (const __half2*)g_wa;

    size_t ou = (size_t)u * 32 + lane;
    size_t oi = (size_t)ni * 32 + lane;

    float sdu = sqrtf((float)g_deg[u]);
    float sdi = sqrtf((float)g_deg[ni]);

    float2 x0u = ((const float2*)Gu)[ou];
    float2 x0i = ((const float2*)Gi)[(size_t)it * 32 + lane];
    float2 a1 = __half22float2(w1[ou]);
    float2 a2 = __half22float2(w2[ou]);
    float2 a3 = __half22float2(w3[ou]);
    float2 b1 = __half22float2(w1[oi]);
    float2 b2 = __half22float2(w2[oi]);
    float2 b3 = __half22float2(w3[oi]);

    float gu0 = 0.25f * (x0u.x + sdu * (a1.x + a2.x + a3.x));
    float gu1 = 0.25f * (x0u.y + sdu * (a1.y + a2.y + a3.y));
    float gi0 = 0.25f * (x0i.x + sdi * (b1.x + b2.x + b3.x));
    float gi1 = 0.25f * (x0i.y + sdi * (b1.y + b2.y + b3.y));

    float2 pv = ((const float2*)g_proj)[(size_t)w * 32 + lane];
    float2 tv = ((const float2*)Tu)[ou];

    float d1 = gu0 * gi0 + gu1 * gi1;
    float ss = pv.x * pv.x + pv.y * pv.y;
    float d2 = tv.x * pv.x + tv.y * pv.y;

    #pragma unroll
    for (int o = 16; o > 0; o >>= 1) {
        d1 += __shfl_xor_sync(0xffffffffu, d1, o);
        ss += __shfl_xor_sync(0xffffffffu, ss, o);
        d2 += __shfl_xor_sync(0xffffffffu, d2, o);
    }
    if (lane == 0) {
        float inv = 1.0f / fmaxf(sqrtf(ss), 1e-12f);
        out[w] = d1 + d2 * inv;
    }
}

// ---------------- launch ----------------
extern "C" void kernel_launch(void* const* d_in, const int* in_sizes, int n_in,
                              void* d_out, int out_size) {
    const float* Gu    = (const float*)d_in[0];
    const float* Gi    = (const float*)d_in[1];
    const float* Tu    = (const float*)d_in[2];
    const float* F     = (const float*)d_in[3];
    const float* W     = (const float*)d_in[4];
    const float* bias  = (const float*)d_in[5];
    const int*   ue    = (const int*)d_in[6];
    const int*   ie    = (const int*)d_in[7];
    const int*   users = (const int*)d_in[8];
    const int*   items = (const int*)d_in[9];
    float*       out   = (float*)d_out;

    (void)in_sizes; (void)n_in; (void)out_size;

    k_zero<<<(NN + 255) / 256, 256>>>();
    k_mark<<<(NB + 255) / 256, 256>>>(users, items);
    k_deg<<<(NE / 4 + 255) / 256, 256>>>(ue, ie);
    k_part<<<NPART, 256>>>();
    k_scanpart<<<1, 1024>>>();
    k_off<<<NPART, 256>>>();
    k_scatter<<<(NE / 4 + 255) / 256, 256>>>(ue, ie);
    k_init<<<(NN * EMB / 4 + 255) / 256, 256>>>(Gu, Gi);

    int prop_threads = ((NN + 3) / 4) * 32;
    int prop_blocks  = (prop_threads + 255) / 256;
    k_prop<<<prop_blocks, 256>>>(0, 0);   // wa -> wb  (w1, all nodes)
    k_prop<<<prop_blocks, 256>>>(1, 0);   // wb -> wc  (w2, all nodes)
    k_prop<<<prop_blocks, 256>>>(2, 1);   // wc -> wa  (w3, batch nodes only)

    k_gemm<<<NB / 64, 256>>>(F, W, bias, items);
    k_score<<<(NB * 32 + 255) / 256, 256>>>(Gu, Gi, Tu, users, items, out);
}

// round 15
// speedup vs baseline: 2.8625x; 1.0898x over previous
#include <cuda_runtime.h>
#include <cuda_fp16.h>
#include <cstdint>

#define NU   100000
#define NI   50000
#define NN   (NU + NI)          // 150000
#define EMB  64
#define NE   3000000            // edges per direction (total dir. edges = 2*NE)
#define FDIM 1024
#define NB   16384
#define NPART ((NN + 255) / 256)   // 586

// ---------------- static device scratch ----------------
__device__ __half g_wa[(size_t)NN * EMB];   // w0, later w3
__device__ __half g_wb[(size_t)NN * EMB];   // w1
__device__ __half g_wc[(size_t)NN * EMB];   // w2
__device__ int   g_deg[NN];
__device__ int   g_off[NN];
__device__ float g_dinv[NN];
__device__ unsigned char g_flag[NN];
__device__ int   g_part[1024];
__device__ int   g_rank_u[NE];
__device__ int   g_rank_i[NE];
__device__ int   g_csr[(size_t)2 * NE];    // src index only
__device__ float g_proj[(size_t)NB * EMB];

// ---------------- graph build ----------------
__global__ void k_zero() {
    int n = blockIdx.x * blockDim.x + threadIdx.x;
    if (n < NN) { g_deg[n] = 0; g_flag[n] = 0; }
}

__global__ void k_mark(const int* __restrict__ users, const int* __restrict__ items) {
    int i = blockIdx.x * blockDim.x + threadIdx.x;
    if (i < NB) {
        g_flag[users[i]] = 1;
        g_flag[NU + items[i]] = 1;
    }
}

// degree count; also captures each edge's rank within its dst segment (reused by scatter)
__global__ void k_deg(const int* __restrict__ ue, const int* __restrict__ ie) {
    int e4 = blockIdx.x * blockDim.x + threadIdx.x;
    if (e4 * 4 + 4 <= NE) {
        int e = e4 * 4;
        int4 u = *(const int4*)(ue + e);
        int4 v = *(const int4*)(ie + e);
        int4 ru, ri;
        ru.x = atomicAdd(&g_deg[u.x], 1);
        ru.y = atomicAdd(&g_deg[u.y], 1);
        ru.z = atomicAdd(&g_deg[u.z], 1);
        ru.w = atomicAdd(&g_deg[u.w], 1);
        ri.x = atomicAdd(&g_deg[v.x + NU], 1);
        ri.y = atomicAdd(&g_deg[v.y + NU], 1);
        ri.z = atomicAdd(&g_deg[v.z + NU], 1);
        ri.w = atomicAdd(&g_deg[v.w + NU], 1);
        *(int4*)(g_rank_u + e) = ru;
        *(int4*)(g_rank_i + e) = ri;
    } else {
        for (int e = e4 * 4; e < NE; e++) {
            g_rank_u[e] = atomicAdd(&g_deg[ue[e]], 1);
            g_rank_i[e] = atomicAdd(&g_deg[ie[e] + NU], 1);
        }
    }
}

// phase A: per-block sum of degrees (also computes dinv)
__global__ void __launch_bounds__(256) k_part() {
    __shared__ int s[256];
    int t = threadIdx.x;
    int n = blockIdx.x * 256 + t;
    int d = (n < NN) ? g_deg[n] : 0;
    if (n < NN) g_dinv[n] = (d > 0) ? rsqrtf((float)d) : 0.0f;
    s[t] = d;
    __syncthreads();
    #pragma unroll
    for (int o = 128; o > 0; o >>= 1) {
        if (t < o) s[t] += s[t + o];
        __syncthreads();
    }
    if (t == 0) g_part[blockIdx.x] = s[0];
}

// phase B: single-block exclusive scan of the partials
__global__ void __launch_bounds__(1024) k_scanpart() {
    __shared__ int s[1024];
    int t = threadIdx.x;
    int v = (t < NPART) ? g_part[t] : 0;
    s[t] = v;
    __syncthreads();
    #pragma unroll
    for (int o = 1; o < 1024; o <<= 1) {
        int u = (t >= o) ? s[t - o] : 0;
        __syncthreads();
        s[t] += u;
        __syncthreads();
    }
    if (t < NPART) g_part[t] = s[t] - v;   // exclusive
}

// phase C: per-block local scan + partial base -> offsets
__global__ void __launch_bounds__(256) k_off() {
    __shared__ int s[256];
    int t = threadIdx.x;
    int n = blockIdx.x * 256 + t;
    int d = (n < NN) ? g_deg[n] : 0;
    s[t] = d;
    __syncthreads();
    #pragma unroll
    for (int o = 1; o < 256; o <<= 1) {
        int u = (t >= o) ? s[t - o] : 0;
        __syncthreads();
        s[t] += u;
        __syncthreads();
    }
    if (n < NN) g_off[n] = g_part[blockIdx.x] + s[t] - d;
}

// scatter with precomputed ranks: no atomics
__global__ void k_scatter(const int* __restrict__ ue, const int* __restrict__ ie) {
    int e4 = blockIdx.x * blockDim.x + threadIdx.x;
    if (e4 * 4 + 4 <= NE) {
        int e = e4 * 4;
        int4 u  = *(const int4*)(ue + e);
        int4 v  = *(const int4*)(ie + e);
        int4 ru = *(const int4*)(g_rank_u + e);
        int4 ri = *(const int4*)(g_rank_i + e);
        g_csr[g_off[v.x + NU] + ri.x] = u.x;
        g_csr[g_off[v.y + NU] + ri.y] = u.y;
        g_csr[g_off[v.z + NU] + ri.z] = u.z;
        g_csr[g_off[v.w + NU] + ri.w] = u.w;
        g_csr[g_off[u.x] + ru.x] = v.x + NU;
        g_csr[g_off[u.y] + ru.y] = v.y + NU;
        g_csr[g_off[u.z] + ru.z] = v.z + NU;
        g_csr[g_off[u.w] + ru.w] = v.w + NU;
    } else {
        for (int e = e4 * 4; e < NE; e++) {
            int u  = ue[e];
            int it = ie[e] + NU;
            g_csr[g_off[it] + g_rank_i[e]] = u;
            g_csr[g_off[u]  + g_rank_u[e]] = it;
        }
    }
}

// w0 = fp16(dinv * x0)
__global__ void k_init(const float* __restrict__ Gu, const float* __restrict__ Gi) {
    int i = blockIdx.x * blockDim.x + threadIdx.x;
    if (i < NN * EMB / 4) {
        int node = i >> 4;   // EMB/4 = 16 float4 per node
        const float4* src = (node < NU) ? (const float4*)Gu
                                        : (const float4*)Gi - (size_t)NU * 16;
        float4 v = src[i];
        float d = g_dinv[node];
        __half2 h0 = __floats2half2_rn(v.x * d, v.y * d);
        __half2 h1 = __floats2half2_rn(v.z * d, v.w * d);
        ((__half2*)g_wa)[2 * i]     = h0;
        ((__half2*)g_wa)[2 * i + 1] = h1;
    }
}

// ---------------- propagation: 4 dst nodes per warp, 8 lanes/node, LDG.128 gathers ----------------
__device__ __forceinline__ void acc8(uint4 q, float* s) {
    float2 v0 = __half22float2(*(__half2*)&q.x);
    float2 v1 = __half22float2(*(__half2*)&q.y);
    float2 v2 = __half22float2(*(__half2*)&q.z);
    float2 v3 = __half22float2(*(__half2*)&q.w);
    s[0] += v0.x; s[1] += v0.y; s[2] += v1.x; s[3] += v1.y;
    s[4] += v2.x; s[5] += v2.y; s[6] += v3.x; s[7] += v3.y;
}

__global__ void __launch_bounds__(256) k_prop(int sel, int pruned) {
    const uint4* __restrict__ xin;
    uint4* __restrict__ xout;
    if (sel == 0)      { xin = (const uint4*)g_wa; xout = (uint4*)g_wb; }
    else if (sel == 1) { xin = (const uint4*)g_wb; xout = (uint4*)g_wc; }
    else               { xin = (const uint4*)g_wc; xout = (uint4*)g_wa; }

    int warpId = (blockIdx.x * blockDim.x + threadIdx.x) >> 5;
    int lane   = threadIdx.x & 31;
    int grp    = lane >> 3;
    int sub    = lane & 7;

    int node = warpId * 4 + grp;
    if (node >= NN) return;
    if (pruned && !g_flag[node]) return;

    int cnt = g_deg[node];
    const int* __restrict__ csr = g_csr + g_off[node];

    float s[8] = {0, 0, 0, 0, 0, 0, 0, 0};
    int i = 0;
    while (i < cnt && (((size_t)(csr + i)) & 15)) {
        int r = csr[i++];
        acc8(xin[(size_t)r * 8 + sub], s);
    }
    for (; i + 8 <= cnt; i += 8) {
        int4 ra = *(const int4*)(csr + i);
        int4 rb = *(const int4*)(csr + i + 4);
        uint4 q0 = xin[(size_t)ra.x * 8 + sub];
        uint4 q1 = xin[(size_t)ra.y * 8 + sub];
        uint4 q2 = xin[(size_t)ra.z * 8 + sub];
        uint4 q3 = xin[(size_t)ra.w * 8 + sub];
        uint4 q4 = xin[(size_t)rb.x * 8 + sub];
        uint4 q5 = xin[(size_t)rb.y * 8 + sub];
        uint4 q6 = xin[(size_t)rb.z * 8 + sub];
        uint4 q7 = xin[(size_t)rb.w * 8 + sub];
        acc8(q0, s); acc8(q1, s); acc8(q2, s); acc8(q3, s);
        acc8(q4, s); acc8(q5, s); acc8(q6, s); acc8(q7, s);
    }
    for (; i + 4 <= cnt; i += 4) {
        int4 r = *(const int4*)(csr + i);
        uint4 q0 = xin[(size_t)r.x * 8 + sub];
        uint4 q1 = xin[(size_t)r.y * 8 + sub];
        uint4 q2 = xin[(size_t)r.z * 8 + sub];
        uint4 q3 = xin[(size_t)r.w * 8 + sub];
        acc8(q0, s); acc8(q1, s); acc8(q2, s); acc8(q3, s);
    }
    for (; i < cnt; i++) {
        int r = csr[i];
        acc8(xin[(size_t)r * 8 + sub], s);
    }

    float d  = g_dinv[node];
    float d2 = d * d;
    __half2 h0 = __floats2half2_rn(s[0] * d2, s[1] * d2);
    __half2 h1 = __floats2half2_rn(s[2] * d2, s[3] * d2);
    __half2 h2 = __floats2half2_rn(s[4] * d2, s[5] * d2);
    __half2 h3 = __floats2half2_rn(s[6] * d2, s[7] * d2);
    uint4 o;
    o.x = *(uint32_t*)&h0; o.y = *(uint32_t*)&h1;
    o.z = *(uint32_t*)&h2; o.w = *(uint32_t*)&h3;
    xout[(size_t)node * 8 + sub] = o;
}

// ---------------- projection GEMM via tensor cores (fp16 hi/lo split, fp32 accum) ----------------
#define MMA16816(C, A, B)                                                        \
    asm volatile("mma.sync.aligned.m16n8k16.row.col.f32.f16.f16.f32 "            \
                 "{%0,%1,%2,%3}, {%4,%5,%6,%7}, {%8,%9}, {%0,%1,%2,%3};"         \
                 : "+f"((C)[0]), "+f"((C)[1]), "+f"((C)[2]), "+f"((C)[3])        \
                 : "r"((A)[0]), "r"((A)[1]), "r"((A)[2]), "r"((A)[3]),           \
                   "r"((B)[0]), "r"((B)[1]))

// pack float4 -> (hi uint2, lo uint2) in fp16
__device__ __forceinline__ void split4(float4 v, uint2& hi, uint2& lo) {
    __half2 hx = __floats2half2_rn(v.x, v.y);
    __half2 hy = __floats2half2_rn(v.z, v.w);
    float2 bx = __half22float2(hx);
    float2 by = __half22float2(hy);
    __half2 lx = __floats2half2_rn(v.x - bx.x, v.y - bx.y);
    __half2 ly = __floats2half2_rn(v.z - by.x, v.w - by.y);
    hi.x = *(uint32_t*)&hx; hi.y = *(uint32_t*)&hy;
    lo.x = *(uint32_t*)&lx; lo.y = *(uint32_t*)&ly;
}

__global__ void __launch_bounds__(256) k_gemm(const float* __restrict__ F,
                                              const float* __restrict__ W,
                                              const float* __restrict__ bias,
                                              const int* __restrict__ items) {
    __shared__ __half sFhi[64][40];
    __shared__ __half sFlo[64][40];
    __shared__ __half sWhi[64][40];
    __shared__ __half sWlo[64][40];
    __shared__ int si[64];

    int t    = threadIdx.x;
    int base = blockIdx.x * 64;
    if (t < 64) si[t] = items[base + t];
    __syncthreads();

    int warp = t >> 5, lane = t & 31;
    int g = lane >> 2, tc = lane & 3;
    int mr    = (warp & 3) * 16;
    int nbase = (warp >> 2) * 32;

    float acc[4][4];
    #pragma unroll
    for (int a = 0; a < 4; a++)
        #pragma unroll
        for (int b = 0; b < 4; b++) acc[a][b] = 0.0f;

    for (int k0 = 0; k0 < FDIM; k0 += 32) {
        #pragma unroll
        for (int j = 0; j < 2; j++) {
            int idx = j * 256 + t;     // 0..511
            int row = idx >> 3;
            int c   = (idx & 7) * 4;
            uint2 hi, lo;
            split4(*(const float4*)(F + (size_t)si[row] * FDIM + k0 + c), hi, lo);
            *(uint2*)&sFhi[row][c] = hi;
            *(uint2*)&sFlo[row][c] = lo;
            split4(*(const float4*)(W + (size_t)row * FDIM + k0 + c), hi, lo);
            *(uint2*)&sWhi[row][c] = hi;
            *(uint2*)&sWlo[row][c] = lo;
        }
        __syncthreads();

        #pragma unroll
        for (int ks = 0; ks < 2; ks++) {
            int kb = ks * 16;
            uint32_t ah[4], al[4];
            ah[0] = *(const uint32_t*)&sFhi[mr + g    ][kb + 2 * tc];
            ah[1] = *(const uint32_t*)&sFhi[mr + g + 8][kb + 2 * tc];
            ah[2] = *(const uint32_t*)&sFhi[mr + g    ][kb + 8 + 2 * tc];
            ah[3] = *(const uint32_t*)&sFhi[mr + g + 8][kb + 8 + 2 * tc];
            al[0] = *(const uint32_t*)&sFlo[mr + g    ][kb + 2 * tc];
            al[1] = *(const uint32_t*)&sFlo[mr + g + 8][kb + 2 * tc];
            al[2] = *(const uint32_t*)&sFlo[mr + g    ][kb + 8 + 2 * tc];
            al[3] = *(const uint32_t*)&sFlo[mr + g + 8][kb + 8 + 2 * tc];
            #pragma unroll
            for (int nt = 0; nt < 4; nt++) {
                int n0 = nbase + nt * 8;
                uint32_t bh[2], bl[2];
                bh[0] = *(const uint32_t*)&sWhi[n0 + g][kb + 2 * tc];
                bh[1] = *(const uint32_t*)&sWhi[n0 + g][kb + 8 + 2 * tc];
                bl[0] = *(const uint32_t*)&sWlo[n0 + g][kb + 2 * tc];
                bl[1] = *(const uint32_t*)&sWlo[n0 + g][kb + 8 + 2 * tc];
                MMA16816(acc[nt], ah, bh);
                MMA16816(acc[nt], ah, bl);
                MMA16816(acc[nt], al, bh);
            }
        }
        __syncthreads();
    }

    #pragma unroll
    for (int nt = 0; nt < 4; nt++) {
        int c0 = nbase + nt * 8 + 2 * tc;
        int r0 = base + mr + g;
        g_proj[(size_t)r0 * EMB + c0]           = acc[nt][0] + bias[c0];
        g_proj[(size_t)r0 * EMB + c0 + 1]       = acc[nt][1] + bias[c0 + 1];
        g_proj[(size_t)(r0 + 8) * EMB + c0]     = acc[nt][2] + bias[c0];
        g_proj[(size_t)(r0 + 8) * EMB + c0 + 1] = acc[nt][3] + bias[c0 + 1];
    }
}

// ---------------- final scoring: one warp per batch element ----------------
__global__ void __launch_bounds__(256) k_score(const float* __restrict__ Gu,
                                               const float* __restrict__ Gi,
                                               const float* __restrict__ Tu,
                                               const int* __restrict__ users,
                                               const int* __restrict__ items,
                                               float* __restrict__ out) {
    int w    = (blockIdx.x * blockDim.x + threadIdx.x) >> 5;
    int lane = threadIdx.x & 31;
    if (w >= NB) return;

    int u  = users[w];
    int it = items[w];
    int ni = NU + it;

    const __half2* w1 = (const __half2*)g_wb;
    const __half2* w2 = (const __half2*)g_wc;
    const __half2* w3 = (const __half2*)g_wa;

    size_t ou = (size_t)u * 32 + lane;
    size_t oi = (size_t)ni * 32 + lane;

    float sdu = sqrtf((float)g_deg[u]);
    float sdi = sqrtf((float)g_deg[ni]);

    float2 x0u = ((const float2*)Gu)[ou];
    float2 x0i = ((const float2*)Gi)[(size_t)it * 32 + lane];
    float2 a1 = __half22float2(w1[ou]);
    float2 a2 = __half22float2(w2[ou]);
    float2 a3 = __half22float2(w3[ou]);
    float2 b1 = __half22float2(w1[oi]);
    float2 b2 = __half22float2(w2[oi]);
    float2 b3 = __half22float2(w3[oi]);

    float gu0 = 0.25f * (x0u.x + sdu * (a1.x + a2.x + a3.x));
    float gu1 = 0.25f * (x0u.y + sdu * (a1.y + a2.y + a3.y));
    float gi0 = 0.25f * (x0i.x + sdi * (b1.x + b2.x + b3.x));
    float gi1 = 0.25f * (x0i.y + sdi * (b1.y + b2.y + b3.y));

    float2 pv = ((const float2*)g_proj)[(size_t)w * 32 + lane];
    float2 tv = ((const float2*)Tu)[ou];

    float d1 = gu0 * gi0 + gu1 * gi1;
    float ss = pv.x * pv.x + pv.y * pv.y;
    float d2 = tv.x * pv.x + tv.y * pv.y;

    #pragma unroll
    for (int o = 16; o > 0; o >>= 1) {
        d1 += __shfl_xor_sync(0xffffffffu, d1, o);
        ss += __shfl_xor_sync(0xffffffffu, ss, o);
        d2 += __shfl_xor_sync(0xffffffffu, d2, o);
    }
    if (lane == 0) {
        float inv = 1.0f / fmaxf(sqrtf(ss), 1e-12f);
        out[w] = d1 + d2 * inv;
    }
}

// ---------------- launch: fork/join so the GEMM overlaps the graph pipeline ----------------
extern "C" void kernel_launch(void* const* d_in, const int* in_sizes, int n_in,
                              void* d_out, int out_size) {
    const float* Gu    = (const float*)d_in[0];
    const float* Gi    = (const float*)d_in[1];
    const float* Tu    = (const float*)d_in[2];
    const float* F     = (const float*)d_in[3];
    const float* W     = (const float*)d_in[4];
    const float* bias  = (const float*)d_in[5];
    const int*   ue    = (const int*)d_in[6];
    const int*   ie    = (const int*)d_in[7];
    const int*   users = (const int*)d_in[8];
    const int*   items = (const int*)d_in[9];
    float*       out   = (float*)d_out;

    (void)in_sizes; (void)n_in; (void)out_size;

    cudaStream_t sA, sB;
    cudaEvent_t eFork, eInitDep, eGemm, eInit, eDone;
    cudaStreamCreateWithFlags(&sA, cudaStreamNonBlocking);
    cudaStreamCreateWithFlags(&sB, cudaStreamNonBlocking);
    cudaEventCreateWithFlags(&eFork,    cudaEventDisableTiming);
    cudaEventCreateWithFlags(&eInitDep, cudaEventDisableTiming);
    cudaEventCreateWithFlags(&eGemm,    cudaEventDisableTiming);
    cudaEventCreateWithFlags(&eInit,    cudaEventDisableTiming);
    cudaEventCreateWithFlags(&eDone,    cudaEventDisableTiming);

    // fork both worker streams off the (captured) default stream
    cudaEventRecord(eFork, 0);
    cudaStreamWaitEvent(sA, eFork, 0);
    cudaStreamWaitEvent(sB, eFork, 0);

    // --- sB: projection GEMM, fully independent of the graph pipeline ---
    k_gemm<<<NB / 64, 256, 0, sB>>>(F, W, bias, items);
    cudaEventRecord(eGemm, sB);

    // --- sA: graph build + propagation ---
    k_zero<<<(NN + 255) / 256, 256, 0, sA>>>();
    k_mark<<<(NB + 255) / 256, 256, 0, sA>>>(users, items);
    k_deg<<<(NE / 4 + 255) / 256, 256, 0, sA>>>(ue, ie);
    k_part<<<NPART, 256, 0, sA>>>();
    cudaEventRecord(eInitDep, sA);            // dinv ready
    k_scanpart<<<1, 1024, 0, sA>>>();
    k_off<<<NPART, 256, 0, sA>>>();
    k_scatter<<<(NE / 4 + 255) / 256, 256, 0, sA>>>(ue, ie);

    // k_init only needs dinv: run it concurrent with scan/off/scatter on sB (after gemm issued)
    cudaStreamWaitEvent(sB, eInitDep, 0);
    k_init<<<(NN * EMB / 4 + 255) / 256, 256, 0, sB>>>(Gu, Gi);
    cudaEventRecord(eInit, sB);
    cudaStreamWaitEvent(sA, eInit, 0);

    int prop_threads = ((NN + 3) / 4) * 32;
    int prop_blocks  = (prop_threads + 255) / 256;
    k_prop<<<prop_blocks, 256, 0, sA>>>(0, 0);   // wa -> wb  (w1)
    k_prop<<<prop_blocks, 256, 0, sA>>>(1, 0);   // wb -> wc  (w2)
    k_prop<<<prop_blocks, 256, 0, sA>>>(2, 1);   // wc -> wa  (w3, batch nodes only)

    // join: score needs props (sA) + gemm (sB)
    cudaStreamWaitEvent(sA, eGemm, 0);
    k_score<<<(NB * 32 + 255) / 256, 256, 0, sA>>>(Gu, Gi, Tu, users, items, out);

    // join worker stream back into the captured origin stream
    cudaEventRecord(eDone, sA);
    cudaStreamWaitEvent(0, eDone, 0);

    cudaEventDestroy(eFork);
    cudaEventDestroy(eInitDep);
    cudaEventDestroy(eGemm);
    cudaEventDestroy(eInit);
    cudaEventDestroy(eDone);
    cudaStreamDestroy(sA);
    cudaStreamDestroy(sB);
}